// round 1
// baseline (speedup 1.0000x reference)
#include <cuda_runtime.h>
#include <math.h>

#define NT      4096       // B*S tokens
#define DMODEL  2048
#define S_LEN   2048
#define BATCH   2
#define HQN     16
#define HKVN    8
#define HD      128
#define NEXP    8
#define FDIM    4096
#define NASSIGN (NT*2)     // top-2 assignments

// ---------------- scratch (device globals; no allocs allowed) ----------------
__device__ float g_lnx [NT*DMODEL];
__device__ float g_q   [NT*DMODEL];
__device__ float g_kbuf[NT*HKVN*HD];
__device__ float g_vbuf[NT*HKVN*HD];
__device__ float g_ctx [NT*DMODEL];
__device__ float g_inter[NT*DMODEL];
__device__ float g_hbuf[NT*DMODEL];
__device__ float g_act0[NASSIGN*FDIM];
__device__ float g_act1[NASSIGN*FDIM];
__device__ float g_eout[NASSIGN*DMODEL];
__device__ int   g_perm[NASSIGN];
__device__ int   g_slot[NASSIGN];
__device__ int   g_tope[NASSIGN];
__device__ float g_wgt [NASSIGN];
__device__ int   g_cnt [NEXP];
__device__ int   g_off [NEXP];

// ---------------- RMSNorm ----------------
__global__ void rmsnorm_k(const float* __restrict__ x, const float* __restrict__ sc,
                          float* __restrict__ y)
{
    int row = blockIdx.x;
    int tid = threadIdx.x;
    const float* xr = x + (size_t)row * DMODEL;
    float ss = 0.f;
    for (int d = tid; d < DMODEL; d += 256) { float v = xr[d]; ss += v * v; }
    __shared__ float red[256];
    red[tid] = ss; __syncthreads();
    for (int st = 128; st > 0; st >>= 1) {
        if (tid < st) red[tid] += red[tid + st];
        __syncthreads();
    }
    float inv = rsqrtf(red[0] / (float)DMODEL + 1e-6f);
    float* yr = y + (size_t)row * DMODEL;
    for (int d = tid; d < DMODEL; d += 256) yr[d] = xr[d] * inv * sc[d];
}

// ---------------- generic SGEMM (optionally bucketed per-expert + row gather) --
// C[rowBase+m, n] = sum_k A[aRow(m), k] * B[k, n]  (+ res)
__global__ __launch_bounds__(256, 2)
void sgemm_k(const float* __restrict__ A, const float* __restrict__ Bg,
             const float* __restrict__ res, float* __restrict__ C,
             int M, int N, int K,
             const int* __restrict__ perm,
             const int* __restrict__ cnts, const int* __restrict__ offs,
             long long strideB)
{
    int rowBase = 0;
    const float* B = Bg;
    if (cnts) {
        int e = blockIdx.z;
        M = cnts[e];
        rowBase = offs[e];
        B = Bg + (long long)e * strideB;
    }
    int bm = blockIdx.y * 128;
    if (bm >= M) return;
    int bn = blockIdx.x * 128;

    __shared__ float As[8][128];
    __shared__ float Bs[8][128];

    int tid = threadIdx.x;
    int tm = (tid >> 4) * 8;         // 0..120
    int tn = (tid & 15) * 8;         // 0..120
    int arow  = tid >> 1;            // 0..127
    int acol0 = (tid & 1) * 4;       // 0 or 4
    int brow  = tid >> 5;            // 0..7
    int bcol  = (tid & 31) * 4;      // 0..124

    int aIdx = -1;
    if (bm + arow < M) {
        int r = rowBase + bm + arow;
        aIdx = perm ? perm[r] : r;
    }

    float acc[8][8];
#pragma unroll
    for (int i = 0; i < 8; i++)
#pragma unroll
        for (int j = 0; j < 8; j++) acc[i][j] = 0.f;

    for (int k0 = 0; k0 < K; k0 += 8) {
        if (aIdx >= 0) {
            float4 av = *(const float4*)&A[(size_t)aIdx * K + k0 + acol0];
            As[acol0 + 0][arow] = av.x;
            As[acol0 + 1][arow] = av.y;
            As[acol0 + 2][arow] = av.z;
            As[acol0 + 3][arow] = av.w;
        } else {
            As[acol0 + 0][arow] = 0.f;
            As[acol0 + 1][arow] = 0.f;
            As[acol0 + 2][arow] = 0.f;
            As[acol0 + 3][arow] = 0.f;
        }
        *(float4*)&Bs[brow][bcol] = *(const float4*)&B[(size_t)(k0 + brow) * N + bn + bcol];
        __syncthreads();
#pragma unroll
        for (int kk = 0; kk < 8; kk++) {
            float a[8], b[8];
            *(float4*)&a[0] = *(const float4*)&As[kk][tm];
            *(float4*)&a[4] = *(const float4*)&As[kk][tm + 4];
            *(float4*)&b[0] = *(const float4*)&Bs[kk][tn];
            *(float4*)&b[4] = *(const float4*)&Bs[kk][tn + 4];
#pragma unroll
            for (int i = 0; i < 8; i++)
#pragma unroll
                for (int j = 0; j < 8; j++)
                    acc[i][j] += a[i] * b[j];
        }
        __syncthreads();
    }

#pragma unroll
    for (int i = 0; i < 8; i++) {
        int rl = bm + tm + i;
        if (rl < M) {
            size_t base = (size_t)(rowBase + rl) * N + bn + tn;
#pragma unroll
            for (int j = 0; j < 8; j += 4) {
                float4 vv = make_float4(acc[i][j], acc[i][j+1], acc[i][j+2], acc[i][j+3]);
                if (res) {
                    float4 rr = *(const float4*)&res[base + j];
                    vv.x += rr.x; vv.y += rr.y; vv.z += rr.z; vv.w += rr.w;
                }
                *(float4*)&C[base + j] = vv;
            }
        }
    }
}

// ---------------- RoPE (in-place, optional scale) ----------------
__global__ void rope_k(float* __restrict__ x, const int* __restrict__ pos,
                       int nheads, float scale, int total)
{
    int idx = blockIdx.x * blockDim.x + threadIdx.x;
    if (idx >= total) return;
    int i   = idx & 63;
    int th  = idx >> 6;
    int h   = th % nheads;
    int tok = th / nheads;
    float freq = powf(10000.0f, -(float)i / 64.0f);
    float ang = (float)pos[tok] * freq;
    float c = cosf(ang), s = sinf(ang);
    float* row = x + (size_t)tok * nheads * HD + h * HD;
    float x1 = row[i], x2 = row[i + 64];
    row[i]      = (x1 * c - x2 * s) * scale;
    row[i + 64] = (x2 * c + x1 * s) * scale;
}

// ---------------- flash attention (fp32, streaming softmax) ----------------
#define QT 32
#define KT 32
#define PADW 132

__global__ void flash_k(const float* __restrict__ Q, const float* __restrict__ Kg,
                        const float* __restrict__ Vg, const int* __restrict__ seg,
                        float* __restrict__ O)
{
    extern __shared__ float sh[];
    float* Qs = sh;                       // QT*PADW
    float* Ks = Qs + QT * PADW;
    float* Vs = Ks + KT * PADW;
    float* Sc = Vs + KT * PADW;           // QT*KT
    float* Mr = Sc + QT * KT;             // QT
    float* Lr = Mr + QT;
    float* Ar = Lr + QT;
    int*   Sq = (int*)(Ar + QT);          // QT
    int*   Sk = Sq + QT;                  // KT

    int tid = threadIdx.x;
    int q0  = blockIdx.x * QT;
    int h   = blockIdx.y;
    int b   = blockIdx.z;
    int tok0 = b * S_LEN;
    int hk  = h >> 1;                     // GQA: 2 q-heads per kv-head

    for (int idx = tid; idx < QT * HD; idx += 256) {
        int r = idx >> 7, d = idx & 127;
        Qs[r * PADW + d] = Q[(size_t)(tok0 + q0 + r) * DMODEL + h * HD + d];
    }
    if (tid < QT) { Sq[tid] = seg[tok0 + q0 + tid]; Mr[tid] = -3.0e38f; Lr[tid] = 0.f; }

    float4 o[4];
#pragma unroll
    for (int c = 0; c < 4; c++) o[c] = make_float4(0.f, 0.f, 0.f, 0.f);
    int i = tid >> 3;                 // output row 0..31
    int dbase = (tid & 7) * 16;       // output dim chunk

    int ktend = (q0 + QT - 1) / KT;
    for (int kt = 0; kt <= ktend; kt++) {
        int k0 = kt * KT;
        __syncthreads();   // protects Qs (first iter) + Ks/Vs/Sc reuse
        for (int idx = tid; idx < KT * HD; idx += 256) {
            int r = idx >> 7, d = idx & 127;
            size_t g = (size_t)(tok0 + k0 + r) * (HKVN * HD) + hk * HD + d;
            Ks[r * PADW + d] = Kg[g];
            Vs[r * PADW + d] = Vg[g];
        }
        if (tid < KT) Sk[tid] = seg[tok0 + k0 + tid];
        __syncthreads();

        {   // scores: thread -> (si, 4 columns)
            int si = tid >> 3;
            int jbase = (tid & 7) * 4;
            const float4* qp = (const float4*)(Qs + si * PADW);
#pragma unroll
            for (int jj = 0; jj < 4; jj++) {
                int j = jbase + jj;
                int qi = q0 + si, kj = k0 + j;
                float sval;
                if (kj > qi || Sq[si] != Sk[j]) {
                    sval = -1e9f;
                } else {
                    const float4* kp = (const float4*)(Ks + j * PADW);
                    float a0 = 0.f;
#pragma unroll
                    for (int d4 = 0; d4 < 32; d4++) {
                        float4 av = qp[d4], cv = kp[d4];
                        a0 += av.x * cv.x + av.y * cv.y + av.z * cv.z + av.w * cv.w;
                    }
                    sval = a0;
                }
                Sc[si * KT + j] = sval;
            }
        }
        __syncthreads();

        if (tid < QT) {   // softmax bookkeeping per row
            int r = tid;
            float mo = Mr[r], mx = mo;
#pragma unroll
            for (int j = 0; j < KT; j++) mx = fmaxf(mx, Sc[r * KT + j]);
            float al = expf(mo - mx);
            float ls = 0.f;
#pragma unroll
            for (int j = 0; j < KT; j++) {
                float p = expf(Sc[r * KT + j] - mx);
                Sc[r * KT + j] = p;
                ls += p;
            }
            Mr[r] = mx;
            Lr[r] = Lr[r] * al + ls;
            Ar[r] = al;
        }
        __syncthreads();

        {   // output accumulation
            float al = Ar[i];
#pragma unroll
            for (int c = 0; c < 4; c++) { o[c].x *= al; o[c].y *= al; o[c].z *= al; o[c].w *= al; }
#pragma unroll
            for (int j = 0; j < KT; j++) {
                float p = Sc[i * KT + j];
                const float4* vp = (const float4*)(Vs + j * PADW + dbase);
#pragma unroll
                for (int c = 0; c < 4; c++) {
                    float4 v = vp[c];
                    o[c].x += p * v.x; o[c].y += p * v.y; o[c].z += p * v.z; o[c].w += p * v.w;
                }
            }
        }
    }

    float linv = 1.0f / Lr[i];
    size_t obase = (size_t)(tok0 + q0 + i) * DMODEL + h * HD + dbase;
#pragma unroll
    for (int c = 0; c < 4; c++) {
        float4 v = o[c];
        v.x *= linv; v.y *= linv; v.z *= linv; v.w *= linv;
        *(float4*)&O[obase + c * 4] = v;
    }
}

// ---------------- gating: logits + top-2 + softmax weights ----------------
__global__ void gate_k(const float* __restrict__ h, const float* __restrict__ gw,
                       int* __restrict__ tope, float* __restrict__ wgt)
{
    int tok = blockIdx.x;
    int tid = threadIdx.x;          // 128 threads
    float s[NEXP];
#pragma unroll
    for (int e = 0; e < NEXP; e++) s[e] = 0.f;
    const float* hr = h + (size_t)tok * DMODEL;
    for (int d = tid; d < DMODEL; d += 128) {
        float hv = hr[d];
#pragma unroll
        for (int e = 0; e < NEXP; e++) s[e] += hv * gw[d * NEXP + e];
    }
    __shared__ float red[NEXP][128];
#pragma unroll
    for (int e = 0; e < NEXP; e++) red[e][tid] = s[e];
    __syncthreads();
    for (int st = 64; st > 0; st >>= 1) {
        if (tid < st)
#pragma unroll
            for (int e = 0; e < NEXP; e++) red[e][tid] += red[e][tid + st];
        __syncthreads();
    }
    if (tid == 0) {
        float l[NEXP];
#pragma unroll
        for (int e = 0; e < NEXP; e++) l[e] = red[e][0];
        int i0 = 0;
#pragma unroll
        for (int e = 1; e < NEXP; e++) if (l[e] > l[i0]) i0 = e;
        int i1 = -1;
#pragma unroll
        for (int e = 0; e < NEXP; e++)
            if (e != i0 && (i1 < 0 || l[e] > l[i1])) i1 = e;
        float z = expf(l[i1] - l[i0]);       // l[i0] >= l[i1]
        float w0 = 1.0f / (1.0f + z);
        tope[tok * 2]     = i0;  wgt[tok * 2]     = w0;
        tope[tok * 2 + 1] = i1;  wgt[tok * 2 + 1] = 1.0f - w0;
    }
}

// ---------------- bucketize assignments by expert (single block) ----------------
__global__ void bucketize_k()
{
    __shared__ int sc[NEXP], cur[NEXP];
    int tid = threadIdx.x;          // 256
    if (tid < NEXP) sc[tid] = 0;
    __syncthreads();
    for (int a = tid; a < NASSIGN; a += 256) atomicAdd(&sc[g_tope[a]], 1);
    __syncthreads();
    if (tid == 0) {
        int o = 0;
        for (int e = 0; e < NEXP; e++) {
            g_cnt[e] = sc[e];
            g_off[e] = o;
            cur[e] = o;
            o += sc[e];
        }
    }
    __syncthreads();
    for (int a = tid; a < NASSIGN; a += 256) {
        int e = g_tope[a];
        int p = atomicAdd(&cur[e], 1);
        g_perm[p] = a >> 1;          // token index
        g_slot[a] = p;               // bucket position for (token,k)
    }
}

// ---------------- SiLU(a0)*a1 in place ----------------
__global__ void silu_mul_k(int total)
{
    int idx = blockIdx.x * blockDim.x + threadIdx.x;
    if (idx >= total) return;
    float a = g_act0[idx];
    float b = g_act1[idx];
    g_act0[idx] = (a / (1.0f + expf(-a))) * b;
}

// ---------------- combine: out = inter + w0*eout[slot0] + w1*eout[slot1] -------
__global__ void combine_k(float* __restrict__ out, int total)
{
    int idx = blockIdx.x * blockDim.x + threadIdx.x;
    if (idx >= total) return;
    int tok = idx >> 11;            // / DMODEL
    int d   = idx & 2047;
    int s0 = g_slot[tok * 2],     s1 = g_slot[tok * 2 + 1];
    float w0 = g_wgt[tok * 2],    w1 = g_wgt[tok * 2 + 1];
    out[idx] = g_inter[idx]
             + w0 * g_eout[(size_t)s0 * DMODEL + d]
             + w1 * g_eout[(size_t)s1 * DMODEL + d];
}

// =============================== launcher ===============================
extern "C" void kernel_launch(void* const* d_in, const int* in_sizes, int n_in,
                              void* d_out, int out_size)
{
    const float* inputs  = (const float*)d_in[0];
    const float* pre_s   = (const float*)d_in[1];
    const float* post_s  = (const float*)d_in[2];
    const float* wq      = (const float*)d_in[3];
    const float* wk      = (const float*)d_in[4];
    const float* wv      = (const float*)d_in[5];
    const float* wo_attn = (const float*)d_in[6];
    const float* gate_w  = (const float*)d_in[7];
    const float* wi0     = (const float*)d_in[8];
    const float* wi1     = (const float*)d_in[9];
    const float* wo_mlp  = (const float*)d_in[10];
    const int*   seg     = (const int*)d_in[11];
    const int*   pos     = (const int*)d_in[12];
    float* out = (float*)d_out;

    float *lnx, *q, *k, *v, *ctx, *inter, *h, *act0, *act1, *eout, *wgt;
    int *perm, *slot, *tope, *cnt, *off;
    cudaGetSymbolAddress((void**)&lnx,  g_lnx);
    cudaGetSymbolAddress((void**)&q,    g_q);
    cudaGetSymbolAddress((void**)&k,    g_kbuf);
    cudaGetSymbolAddress((void**)&v,    g_vbuf);
    cudaGetSymbolAddress((void**)&ctx,  g_ctx);
    cudaGetSymbolAddress((void**)&inter,g_inter);
    cudaGetSymbolAddress((void**)&h,    g_hbuf);
    cudaGetSymbolAddress((void**)&act0, g_act0);
    cudaGetSymbolAddress((void**)&act1, g_act1);
    cudaGetSymbolAddress((void**)&eout, g_eout);
    cudaGetSymbolAddress((void**)&perm, g_perm);
    cudaGetSymbolAddress((void**)&slot, g_slot);
    cudaGetSymbolAddress((void**)&tope, g_tope);
    cudaGetSymbolAddress((void**)&wgt,  g_wgt);
    cudaGetSymbolAddress((void**)&cnt,  g_cnt);
    cudaGetSymbolAddress((void**)&off,  g_off);

    const size_t FLASH_SMEM = (size_t)(3 * QT * PADW + QT * KT + 3 * QT) * sizeof(float)
                            + (size_t)(QT + KT) * sizeof(int);
    cudaFuncSetAttribute(flash_k, cudaFuncAttributeMaxDynamicSharedMemorySize,
                         (int)FLASH_SMEM);

    // 1) pre-attention RMSNorm
    rmsnorm_k<<<NT, 256>>>(inputs, pre_s, lnx);

    // 2) QKV projections
    sgemm_k<<<dim3(DMODEL/128, NT/128, 1), 256>>>(lnx, wq, nullptr, q,
        NT, DMODEL, DMODEL, nullptr, nullptr, nullptr, 0);
    sgemm_k<<<dim3((HKVN*HD)/128, NT/128, 1), 256>>>(lnx, wk, nullptr, k,
        NT, HKVN*HD, DMODEL, nullptr, nullptr, nullptr, 0);
    sgemm_k<<<dim3((HKVN*HD)/128, NT/128, 1), 256>>>(lnx, wv, nullptr, v,
        NT, HKVN*HD, DMODEL, nullptr, nullptr, nullptr, 0);

    // 3) RoPE (q scaled by hd^-0.5, k unscaled)
    {
        int totq = NT * HQN * 64;
        rope_k<<<(totq + 255) / 256, 256>>>(q, pos, HQN, 0.08838834764831845f, totq);
        int totk = NT * HKVN * 64;
        rope_k<<<(totk + 255) / 256, 256>>>(k, pos, HKVN, 1.0f, totk);
    }

    // 4) flash attention -> ctx
    flash_k<<<dim3(S_LEN/QT, HQN, BATCH), 256, FLASH_SMEM>>>(q, k, v, seg, ctx);

    // 5) O projection + residual -> inter
    sgemm_k<<<dim3(DMODEL/128, NT/128, 1), 256>>>(ctx, wo_attn, inputs, inter,
        NT, DMODEL, DMODEL, nullptr, nullptr, nullptr, 0);

    // 6) post-attention RMSNorm -> h
    rmsnorm_k<<<NT, 256>>>(inter, post_s, h);

    // 7) gating (top-2 + softmax weights)
    gate_k<<<NT, 128>>>(h, gate_w, tope, wgt);

    // 8) bucketize assignments by expert
    bucketize_k<<<1, 256>>>();

    // 9) MoE up-projections (gathered rows, per-expert B)
    sgemm_k<<<dim3(FDIM/128, NASSIGN/128, NEXP), 256>>>(h, wi0, nullptr, act0,
        0, FDIM, DMODEL, perm, cnt, off, (long long)DMODEL * FDIM);
    sgemm_k<<<dim3(FDIM/128, NASSIGN/128, NEXP), 256>>>(h, wi1, nullptr, act1,
        0, FDIM, DMODEL, perm, cnt, off, (long long)DMODEL * FDIM);

    // 10) SiLU(act0) * act1 -> act0
    silu_mul_k<<<(NASSIGN * FDIM) / 256, 256>>>(NASSIGN * FDIM);

    // 11) MoE down-projection (bucket rows, per-expert B)
    sgemm_k<<<dim3(DMODEL/128, NASSIGN/128, NEXP), 256>>>(act0, wo_mlp, nullptr, eout,
        0, DMODEL, FDIM, nullptr, cnt, off, (long long)FDIM * DMODEL);

    // 12) combine: out = inter + w0*e0 + w1*e1
    combine_k<<<(NT * DMODEL) / 256, 256>>>(out, NT * DMODEL);
}

// round 2
// speedup vs baseline: 1.1522x; 1.1522x over previous
#include <cuda_runtime.h>
#include <cstdint>
#include <math.h>

#define NT      4096       // B*S tokens
#define DMODEL  2048
#define S_LEN   2048
#define BATCH   2
#define HQN     16
#define HKVN    8
#define HD      128
#define NEXP    8
#define FDIM    4096
#define NASSIGN (NT*2)     // top-2 assignments

// ---------------- scratch (device globals; no allocs allowed) ----------------
__device__ float g_lnx [NT*DMODEL];
__device__ float g_q   [NT*DMODEL];
__device__ float g_kbuf[NT*HKVN*HD];
__device__ float g_vbuf[NT*HKVN*HD];
__device__ float g_ctx [NT*DMODEL];
__device__ float g_inter[NT*DMODEL];
__device__ float g_hbuf[NT*DMODEL];
__device__ float g_act0[NASSIGN*FDIM];
__device__ float g_act1[NASSIGN*FDIM];
__device__ float g_eout[NASSIGN*DMODEL];
__device__ int   g_perm[NASSIGN];
__device__ int   g_slot[NASSIGN];
__device__ int   g_tope[NASSIGN];
__device__ float g_wgt [NASSIGN];
__device__ int   g_cnt [NEXP];
__device__ int   g_off [NEXP];

// ---------------- RMSNorm ----------------
__global__ void rmsnorm_k(const float* __restrict__ x, const float* __restrict__ sc,
                          float* __restrict__ y)
{
    int row = blockIdx.x;
    int tid = threadIdx.x;
    const float* xr = x + (size_t)row * DMODEL;
    float ss = 0.f;
    for (int d = tid; d < DMODEL; d += 256) { float v = xr[d]; ss += v * v; }
    __shared__ float red[256];
    red[tid] = ss; __syncthreads();
    for (int st = 128; st > 0; st >>= 1) {
        if (tid < st) red[tid] += red[tid + st];
        __syncthreads();
    }
    float inv = rsqrtf(red[0] / (float)DMODEL + 1e-6f);
    float* yr = y + (size_t)row * DMODEL;
    for (int d = tid; d < DMODEL; d += 256) yr[d] = xr[d] * inv * sc[d];
}

// ================= TF32x3 tensor-core GEMM =================
// C[rowBase+m, n] = sum_k A[aRow(m), k] * B[k, n]  (+ res)
// BM=128, BN=128, BK=16; 8 warps, warp tile 64x32; mma.m16n8k8.tf32 x3 split.
#define BKP 20     // A smem row stride (floats) -> conflict-free frag loads
#define BNP 136    // B smem row stride (floats) -> conflict-free frag loads

__device__ __forceinline__ uint32_t f2tf32(float x) {
    uint32_t u;
    asm("cvt.rna.tf32.f32 %0, %1;" : "=r"(u) : "f"(x));
    return u;
}

__device__ __forceinline__ void mma_tf32(float* c, const uint32_t* a, const uint32_t* b) {
    asm volatile(
        "mma.sync.aligned.m16n8k8.row.col.f32.tf32.tf32.f32 "
        "{%0,%1,%2,%3}, {%4,%5,%6,%7}, {%8,%9}, {%0,%1,%2,%3};"
        : "+f"(c[0]), "+f"(c[1]), "+f"(c[2]), "+f"(c[3])
        : "r"(a[0]), "r"(a[1]), "r"(a[2]), "r"(a[3]), "r"(b[0]), "r"(b[1]));
}

__device__ __forceinline__ void cp16(uint32_t dst, const void* src) {
    asm volatile("cp.async.cg.shared.global [%0], [%1], 16;" :: "r"(dst), "l"(src));
}
__device__ __forceinline__ void cp16_zero(uint32_t dst, const void* src) {
    asm volatile("cp.async.cg.shared.global [%0], [%1], 16, 0;" :: "r"(dst), "l"(src));
}

__global__ __launch_bounds__(256, 1)
void mma_gemm_k(const float* __restrict__ A, const float* __restrict__ Bg,
                const float* __restrict__ res, float* __restrict__ C,
                int M, int N, int K,
                const int* __restrict__ perm,
                const int* __restrict__ cnts, const int* __restrict__ offs,
                long long strideB)
{
    int rowBase = 0;
    const float* B = Bg;
    if (cnts) {
        int e = blockIdx.z;
        M = cnts[e];
        rowBase = offs[e];
        B = Bg + (long long)e * strideB;
    }
    int bm = blockIdx.y * 128;
    if (bm >= M) return;
    int bn = blockIdx.x * 128;

    __shared__ float As[2][128][BKP];
    __shared__ float Bs[2][16][BNP];

    int tid  = threadIdx.x;
    int lane = tid & 31;
    int w    = tid >> 5;
    int wm   = w & 1;          // 2 warps along M
    int wn   = w >> 1;         // 4 warps along N
    int g    = lane >> 2;      // group id 0..7
    int tig  = lane & 3;       // thread-in-group 0..3

    // A gather rows for this thread's two load chunks
    int r0 = tid >> 2;                  // 0..63
    int r1 = r0 + 64;                   // 64..127
    int c4 = (tid & 3) * 4;             // k-chunk within BK
    int aIdx0 = -1, aIdx1 = -1;
    if (bm + r0 < M) { int r = rowBase + bm + r0; aIdx0 = perm ? perm[r] : r; }
    if (bm + r1 < M) { int r = rowBase + bm + r1; aIdx1 = perm ? perm[r] : r; }

    // B load coords: two chunks
    int br0 = tid >> 5;                 // 0..7
    int br1 = br0 + 8;                  // 8..15
    int bc4 = (tid & 31) * 4;

    float acc[4][4][4];
#pragma unroll
    for (int i = 0; i < 4; i++)
#pragma unroll
        for (int j = 0; j < 4; j++)
#pragma unroll
            for (int c = 0; c < 4; c++) acc[i][j][c] = 0.f;

    const int NKT = K >> 4;

    // ---- prefetch helper (macro-style lambda) ----
    auto prefetch = [&](int kt, int st) {
        int k0 = kt << 4;
        uint32_t dA0 = (uint32_t)__cvta_generic_to_shared(&As[st][r0][c4]);
        uint32_t dA1 = (uint32_t)__cvta_generic_to_shared(&As[st][r1][c4]);
        if (aIdx0 >= 0) cp16(dA0, &A[(size_t)aIdx0 * K + k0 + c4]);
        else            cp16_zero(dA0, A);
        if (aIdx1 >= 0) cp16(dA1, &A[(size_t)aIdx1 * K + k0 + c4]);
        else            cp16_zero(dA1, A);
        uint32_t dB0 = (uint32_t)__cvta_generic_to_shared(&Bs[st][br0][bc4]);
        uint32_t dB1 = (uint32_t)__cvta_generic_to_shared(&Bs[st][br1][bc4]);
        cp16(dB0, &B[(size_t)(k0 + br0) * N + bn + bc4]);
        cp16(dB1, &B[(size_t)(k0 + br1) * N + bn + bc4]);
    };

    prefetch(0, 0);
    asm volatile("cp.async.commit_group;" ::: "memory");

    for (int kt = 0; kt < NKT; kt++) {
        int st = kt & 1;
        if (kt + 1 < NKT) {
            prefetch(kt + 1, st ^ 1);
            asm volatile("cp.async.commit_group;" ::: "memory");
            asm volatile("cp.async.wait_group 1;" ::: "memory");
        } else {
            asm volatile("cp.async.wait_group 0;" ::: "memory");
        }
        __syncthreads();

#pragma unroll
        for (int ks = 0; ks < 2; ks++) {
            const int kk = ks * 8;
            uint32_t ah[4][4], al[4][4];
#pragma unroll
            for (int mf = 0; mf < 4; mf++) {
                int rr = wm * 64 + mf * 16 + g;
                float f0 = As[st][rr][kk + tig];
                float f1 = As[st][rr + 8][kk + tig];
                float f2 = As[st][rr][kk + tig + 4];
                float f3 = As[st][rr + 8][kk + tig + 4];
                ah[mf][0] = f2tf32(f0); al[mf][0] = f2tf32(f0 - __uint_as_float(ah[mf][0]));
                ah[mf][1] = f2tf32(f1); al[mf][1] = f2tf32(f1 - __uint_as_float(ah[mf][1]));
                ah[mf][2] = f2tf32(f2); al[mf][2] = f2tf32(f2 - __uint_as_float(ah[mf][2]));
                ah[mf][3] = f2tf32(f3); al[mf][3] = f2tf32(f3 - __uint_as_float(ah[mf][3]));
            }
            uint32_t bh[4][2], bl[4][2];
#pragma unroll
            for (int nf = 0; nf < 4; nf++) {
                int cb = wn * 32 + nf * 8 + g;
                float f0 = Bs[st][kk + tig][cb];
                float f1 = Bs[st][kk + tig + 4][cb];
                bh[nf][0] = f2tf32(f0); bl[nf][0] = f2tf32(f0 - __uint_as_float(bh[nf][0]));
                bh[nf][1] = f2tf32(f1); bl[nf][1] = f2tf32(f1 - __uint_as_float(bh[nf][1]));
            }
            // term 0: a_lo * b_hi   (16 independent mmas)
#pragma unroll
            for (int mf = 0; mf < 4; mf++)
#pragma unroll
                for (int nf = 0; nf < 4; nf++)
                    mma_tf32(acc[mf][nf], al[mf], bh[nf]);
            // term 1: a_hi * b_lo
#pragma unroll
            for (int mf = 0; mf < 4; mf++)
#pragma unroll
                for (int nf = 0; nf < 4; nf++)
                    mma_tf32(acc[mf][nf], ah[mf], bl[nf]);
            // term 2: a_hi * b_hi
#pragma unroll
            for (int mf = 0; mf < 4; mf++)
#pragma unroll
                for (int nf = 0; nf < 4; nf++)
                    mma_tf32(acc[mf][nf], ah[mf], bh[nf]);
        }
        __syncthreads();
    }

    // ---- store ----
#pragma unroll
    for (int mf = 0; mf < 4; mf++) {
        int row0 = bm + wm * 64 + mf * 16 + g;
        int row1 = row0 + 8;
#pragma unroll
        for (int nf = 0; nf < 4; nf++) {
            int col = bn + wn * 32 + nf * 8 + tig * 2;
            if (row0 < M) {
                size_t o = (size_t)(rowBase + row0) * N + col;
                float2 v = make_float2(acc[mf][nf][0], acc[mf][nf][1]);
                if (res) { float2 r = *(const float2*)&res[o]; v.x += r.x; v.y += r.y; }
                *(float2*)&C[o] = v;
            }
            if (row1 < M) {
                size_t o = (size_t)(rowBase + row1) * N + col;
                float2 v = make_float2(acc[mf][nf][2], acc[mf][nf][3]);
                if (res) { float2 r = *(const float2*)&res[o]; v.x += r.x; v.y += r.y; }
                *(float2*)&C[o] = v;
            }
        }
    }
}

// ---------------- RoPE (in-place, optional scale) ----------------
__global__ void rope_k(float* __restrict__ x, const int* __restrict__ pos,
                       int nheads, float scale, int total)
{
    int idx = blockIdx.x * blockDim.x + threadIdx.x;
    if (idx >= total) return;
    int i   = idx & 63;
    int th  = idx >> 6;
    int h   = th % nheads;
    int tok = th / nheads;
    float freq = powf(10000.0f, -(float)i / 64.0f);
    float ang = (float)pos[tok] * freq;
    float c = cosf(ang), s = sinf(ang);
    float* row = x + (size_t)tok * nheads * HD + h * HD;
    float x1 = row[i], x2 = row[i + 64];
    row[i]      = (x1 * c - x2 * s) * scale;
    row[i + 64] = (x2 * c + x1 * s) * scale;
}

// ---------------- flash attention (fp32, streaming softmax) ----------------
#define QT 32
#define KT 32
#define PADW 132

__global__ void flash_k(const float* __restrict__ Q, const float* __restrict__ Kg,
                        const float* __restrict__ Vg, const int* __restrict__ seg,
                        float* __restrict__ O)
{
    extern __shared__ float sh[];
    float* Qs = sh;                       // QT*PADW
    float* Ks = Qs + QT * PADW;
    float* Vs = Ks + KT * PADW;
    float* Sc = Vs + KT * PADW;           // QT*KT
    float* Mr = Sc + QT * KT;             // QT
    float* Lr = Mr + QT;
    float* Ar = Lr + QT;
    int*   Sq = (int*)(Ar + QT);          // QT
    int*   Sk = Sq + QT;                  // KT

    int tid = threadIdx.x;
    int q0  = blockIdx.x * QT;
    int h   = blockIdx.y;
    int b   = blockIdx.z;
    int tok0 = b * S_LEN;
    int hk  = h >> 1;                     // GQA: 2 q-heads per kv-head

    for (int idx = tid; idx < QT * HD; idx += 256) {
        int r = idx >> 7, d = idx & 127;
        Qs[r * PADW + d] = Q[(size_t)(tok0 + q0 + r) * DMODEL + h * HD + d];
    }
    if (tid < QT) { Sq[tid] = seg[tok0 + q0 + tid]; Mr[tid] = -3.0e38f; Lr[tid] = 0.f; }

    float4 o[4];
#pragma unroll
    for (int c = 0; c < 4; c++) o[c] = make_float4(0.f, 0.f, 0.f, 0.f);
    int i = tid >> 3;                 // output row 0..31
    int dbase = (tid & 7) * 16;       // output dim chunk

    int ktend = (q0 + QT - 1) / KT;
    for (int kt = 0; kt <= ktend; kt++) {
        int k0 = kt * KT;
        __syncthreads();   // protects Qs (first iter) + Ks/Vs/Sc reuse
        for (int idx = tid; idx < KT * HD; idx += 256) {
            int r = idx >> 7, d = idx & 127;
            size_t gg = (size_t)(tok0 + k0 + r) * (HKVN * HD) + hk * HD + d;
            Ks[r * PADW + d] = Kg[gg];
            Vs[r * PADW + d] = Vg[gg];
        }
        if (tid < KT) Sk[tid] = seg[tok0 + k0 + tid];
        __syncthreads();

        {   // scores: thread -> (si, 4 columns)
            int si = tid >> 3;
            int jbase = (tid & 7) * 4;
            const float4* qp = (const float4*)(Qs + si * PADW);
#pragma unroll
            for (int jj = 0; jj < 4; jj++) {
                int j = jbase + jj;
                int qi = q0 + si, kj = k0 + j;
                float sval;
                if (kj > qi || Sq[si] != Sk[j]) {
                    sval = -1e9f;
                } else {
                    const float4* kp = (const float4*)(Ks + j * PADW);
                    float a0 = 0.f;
#pragma unroll
                    for (int d4 = 0; d4 < 32; d4++) {
                        float4 av = qp[d4], cv = kp[d4];
                        a0 += av.x * cv.x + av.y * cv.y + av.z * cv.z + av.w * cv.w;
                    }
                    sval = a0;
                }
                Sc[si * KT + j] = sval;
            }
        }
        __syncthreads();

        if (tid < QT) {   // softmax bookkeeping per row
            int r = tid;
            float mo = Mr[r], mx = mo;
#pragma unroll
            for (int j = 0; j < KT; j++) mx = fmaxf(mx, Sc[r * KT + j]);
            float al = expf(mo - mx);
            float ls = 0.f;
#pragma unroll
            for (int j = 0; j < KT; j++) {
                float p = expf(Sc[r * KT + j] - mx);
                Sc[r * KT + j] = p;
                ls += p;
            }
            Mr[r] = mx;
            Lr[r] = Lr[r] * al + ls;
            Ar[r] = al;
        }
        __syncthreads();

        {   // output accumulation
            float al = Ar[i];
#pragma unroll
            for (int c = 0; c < 4; c++) { o[c].x *= al; o[c].y *= al; o[c].z *= al; o[c].w *= al; }
#pragma unroll
            for (int j = 0; j < KT; j++) {
                float p = Sc[i * KT + j];
                const float4* vp = (const float4*)(Vs + j * PADW + dbase);
#pragma unroll
                for (int c = 0; c < 4; c++) {
                    float4 v = vp[c];
                    o[c].x += p * v.x; o[c].y += p * v.y; o[c].z += p * v.z; o[c].w += p * v.w;
                }
            }
        }
    }

    float linv = 1.0f / Lr[i];
    size_t obase = (size_t)(tok0 + q0 + i) * DMODEL + h * HD + dbase;
#pragma unroll
    for (int c = 0; c < 4; c++) {
        float4 v = o[c];
        v.x *= linv; v.y *= linv; v.z *= linv; v.w *= linv;
        *(float4*)&O[obase + c * 4] = v;
    }
}

// ---------------- gating: logits + top-2 + softmax weights ----------------
__global__ void gate_k(const float* __restrict__ h, const float* __restrict__ gw,
                       int* __restrict__ tope, float* __restrict__ wgt)
{
    int tok = blockIdx.x;
    int tid = threadIdx.x;          // 128 threads
    float s[NEXP];
#pragma unroll
    for (int e = 0; e < NEXP; e++) s[e] = 0.f;
    const float* hr = h + (size_t)tok * DMODEL;
    for (int d = tid; d < DMODEL; d += 128) {
        float hv = hr[d];
#pragma unroll
        for (int e = 0; e < NEXP; e++) s[e] += hv * gw[d * NEXP + e];
    }
    __shared__ float red[NEXP][128];
#pragma unroll
    for (int e = 0; e < NEXP; e++) red[e][tid] = s[e];
    __syncthreads();
    for (int st = 64; st > 0; st >>= 1) {
        if (tid < st)
#pragma unroll
            for (int e = 0; e < NEXP; e++) red[e][tid] += red[e][tid + st];
        __syncthreads();
    }
    if (tid == 0) {
        float l[NEXP];
#pragma unroll
        for (int e = 0; e < NEXP; e++) l[e] = red[e][0];
        int i0 = 0;
#pragma unroll
        for (int e = 1; e < NEXP; e++) if (l[e] > l[i0]) i0 = e;
        int i1 = -1;
#pragma unroll
        for (int e = 0; e < NEXP; e++)
            if (e != i0 && (i1 < 0 || l[e] > l[i1])) i1 = e;
        float z = expf(l[i1] - l[i0]);       // l[i0] >= l[i1]
        float w0 = 1.0f / (1.0f + z);
        tope[tok * 2]     = i0;  wgt[tok * 2]     = w0;
        tope[tok * 2 + 1] = i1;  wgt[tok * 2 + 1] = 1.0f - w0;
    }
}

// ---------------- bucketize assignments by expert (single block) ----------------
__global__ void bucketize_k()
{
    __shared__ int sc[NEXP], cur[NEXP];
    int tid = threadIdx.x;          // 256
    if (tid < NEXP) sc[tid] = 0;
    __syncthreads();
    for (int a = tid; a < NASSIGN; a += 256) atomicAdd(&sc[g_tope[a]], 1);
    __syncthreads();
    if (tid == 0) {
        int o = 0;
        for (int e = 0; e < NEXP; e++) {
            g_cnt[e] = sc[e];
            g_off[e] = o;
            cur[e] = o;
            o += sc[e];
        }
    }
    __syncthreads();
    for (int a = tid; a < NASSIGN; a += 256) {
        int e = g_tope[a];
        int p = atomicAdd(&cur[e], 1);
        g_perm[p] = a >> 1;          // token index
        g_slot[a] = p;               // bucket position for (token,k)
    }
}

// ---------------- SiLU(a0)*a1 in place ----------------
__global__ void silu_mul_k(int total)
{
    int idx = blockIdx.x * blockDim.x + threadIdx.x;
    if (idx >= total) return;
    float a = g_act0[idx];
    float b = g_act1[idx];
    g_act0[idx] = (a / (1.0f + expf(-a))) * b;
}

// ---------------- combine: out = inter + w0*eout[slot0] + w1*eout[slot1] -------
__global__ void combine_k(float* __restrict__ out, int total)
{
    int idx = blockIdx.x * blockDim.x + threadIdx.x;
    if (idx >= total) return;
    int tok = idx >> 11;            // / DMODEL
    int d   = idx & 2047;
    int s0 = g_slot[tok * 2],     s1 = g_slot[tok * 2 + 1];
    float w0 = g_wgt[tok * 2],    w1 = g_wgt[tok * 2 + 1];
    out[idx] = g_inter[idx]
             + w0 * g_eout[(size_t)s0 * DMODEL + d]
             + w1 * g_eout[(size_t)s1 * DMODEL + d];
}

// =============================== launcher ===============================
extern "C" void kernel_launch(void* const* d_in, const int* in_sizes, int n_in,
                              void* d_out, int out_size)
{
    const float* inputs  = (const float*)d_in[0];
    const float* pre_s   = (const float*)d_in[1];
    const float* post_s  = (const float*)d_in[2];
    const float* wq      = (const float*)d_in[3];
    const float* wk      = (const float*)d_in[4];
    const float* wv      = (const float*)d_in[5];
    const float* wo_attn = (const float*)d_in[6];
    const float* gate_w  = (const float*)d_in[7];
    const float* wi0     = (const float*)d_in[8];
    const float* wi1     = (const float*)d_in[9];
    const float* wo_mlp  = (const float*)d_in[10];
    const int*   seg     = (const int*)d_in[11];
    const int*   pos     = (const int*)d_in[12];
    float* out = (float*)d_out;

    float *lnx, *q, *k, *v, *ctx, *inter, *h, *act0, *act1, *eout, *wgt;
    int *perm, *slot, *tope, *cnt, *off;
    cudaGetSymbolAddress((void**)&lnx,  g_lnx);
    cudaGetSymbolAddress((void**)&q,    g_q);
    cudaGetSymbolAddress((void**)&k,    g_kbuf);
    cudaGetSymbolAddress((void**)&v,    g_vbuf);
    cudaGetSymbolAddress((void**)&ctx,  g_ctx);
    cudaGetSymbolAddress((void**)&inter,g_inter);
    cudaGetSymbolAddress((void**)&h,    g_hbuf);
    cudaGetSymbolAddress((void**)&act0, g_act0);
    cudaGetSymbolAddress((void**)&act1, g_act1);
    cudaGetSymbolAddress((void**)&eout, g_eout);
    cudaGetSymbolAddress((void**)&perm, g_perm);
    cudaGetSymbolAddress((void**)&slot, g_slot);
    cudaGetSymbolAddress((void**)&tope, g_tope);
    cudaGetSymbolAddress((void**)&wgt,  g_wgt);
    cudaGetSymbolAddress((void**)&cnt,  g_cnt);
    cudaGetSymbolAddress((void**)&off,  g_off);

    const size_t FLASH_SMEM = (size_t)(3 * QT * PADW + QT * KT + 3 * QT) * sizeof(float)
                            + (size_t)(QT + KT) * sizeof(int);
    cudaFuncSetAttribute(flash_k, cudaFuncAttributeMaxDynamicSharedMemorySize,
                         (int)FLASH_SMEM);

    // 1) pre-attention RMSNorm
    rmsnorm_k<<<NT, 256>>>(inputs, pre_s, lnx);

    // 2) QKV projections (tensor-core tf32x3)
    mma_gemm_k<<<dim3(DMODEL/128, NT/128, 1), 256>>>(lnx, wq, nullptr, q,
        NT, DMODEL, DMODEL, nullptr, nullptr, nullptr, 0);
    mma_gemm_k<<<dim3((HKVN*HD)/128, NT/128, 1), 256>>>(lnx, wk, nullptr, k,
        NT, HKVN*HD, DMODEL, nullptr, nullptr, nullptr, 0);
    mma_gemm_k<<<dim3((HKVN*HD)/128, NT/128, 1), 256>>>(lnx, wv, nullptr, v,
        NT, HKVN*HD, DMODEL, nullptr, nullptr, nullptr, 0);

    // 3) RoPE (q scaled by hd^-0.5, k unscaled)
    {
        int totq = NT * HQN * 64;
        rope_k<<<(totq + 255) / 256, 256>>>(q, pos, HQN, 0.08838834764831845f, totq);
        int totk = NT * HKVN * 64;
        rope_k<<<(totk + 255) / 256, 256>>>(k, pos, HKVN, 1.0f, totk);
    }

    // 4) flash attention -> ctx
    flash_k<<<dim3(S_LEN/QT, HQN, BATCH), 256, FLASH_SMEM>>>(q, k, v, seg, ctx);

    // 5) O projection + residual -> inter
    mma_gemm_k<<<dim3(DMODEL/128, NT/128, 1), 256>>>(ctx, wo_attn, inputs, inter,
        NT, DMODEL, DMODEL, nullptr, nullptr, nullptr, 0);

    // 6) post-attention RMSNorm -> h
    rmsnorm_k<<<NT, 256>>>(inter, post_s, h);

    // 7) gating (top-2 + softmax weights)
    gate_k<<<NT, 128>>>(h, gate_w, tope, wgt);

    // 8) bucketize assignments by expert
    bucketize_k<<<1, 256>>>();

    // 9) MoE up-projections (gathered rows, per-expert B)
    mma_gemm_k<<<dim3(FDIM/128, NASSIGN/128, NEXP), 256>>>(h, wi0, nullptr, act0,
        0, FDIM, DMODEL, perm, cnt, off, (long long)DMODEL * FDIM);
    mma_gemm_k<<<dim3(FDIM/128, NASSIGN/128, NEXP), 256>>>(h, wi1, nullptr, act1,
        0, FDIM, DMODEL, perm, cnt, off, (long long)DMODEL * FDIM);

    // 10) SiLU(act0) * act1 -> act0
    silu_mul_k<<<(NASSIGN * FDIM) / 256, 256>>>(NASSIGN * FDIM);

    // 11) MoE down-projection (bucket rows, per-expert B)
    mma_gemm_k<<<dim3(DMODEL/128, NASSIGN/128, NEXP), 256>>>(act0, wo_mlp, nullptr, eout,
        0, DMODEL, FDIM, nullptr, cnt, off, (long long)FDIM * DMODEL);

    // 12) combine: out = inter + w0*e0 + w1*e1
    combine_k<<<(NT * DMODEL) / 256, 256>>>(out, NT * DMODEL);
}

// round 3
// speedup vs baseline: 1.4841x; 1.2880x over previous
#include <cuda_runtime.h>
#include <cuda_bf16.h>
#include <cstdint>
#include <math.h>

#define NT      4096       // B*S tokens
#define DMODEL  2048
#define S_LEN   2048
#define BATCH   2
#define HQN     16
#define HKVN    8
#define HD      128
#define NEXP    8
#define FDIM    4096
#define NASSIGN (NT*2)
#define QKVN    4096       // 2048 q + 1024 k + 1024 v

typedef __nv_bfloat16 bf16;

// ---------------- scratch ----------------
__device__ float g_qkv [NT*QKVN];
__device__ float g_inter[NT*DMODEL];
__device__ float g_hbuf[NT*DMODEL];
__device__ float g_act0[NASSIGN*FDIM];
__device__ float g_act1[NASSIGN*FDIM];
__device__ float g_eout[NASSIGN*DMODEL];
__device__ int   g_perm[NASSIGN];
__device__ int   g_slot[NASSIGN];
__device__ int   g_tope[NASSIGN];
__device__ float g_wgt [NASSIGN];
__device__ int   g_cnt [NEXP];
__device__ int   g_off [NEXP];

// bf16 hi/lo operand arrays
__device__ bf16 g_lnxh[NT*DMODEL],  g_lnxl[NT*DMODEL];
__device__ bf16 g_cth [NT*DMODEL],  g_ctl [NT*DMODEL];
__device__ bf16 g_hh  [NT*DMODEL],  g_hl  [NT*DMODEL];
__device__ bf16 g_acth[NASSIGN*FDIM], g_actl[NASSIGN*FDIM];
__device__ bf16 g_qkvwh[DMODEL*QKVN], g_qkvwl[DMODEL*QKVN];
__device__ bf16 g_woh [DMODEL*DMODEL], g_wol [DMODEL*DMODEL];
__device__ bf16 g_wi0h[NEXP*DMODEL*FDIM], g_wi0l[NEXP*DMODEL*FDIM];
__device__ bf16 g_wi1h[NEXP*DMODEL*FDIM], g_wi1l[NEXP*DMODEL*FDIM];
__device__ bf16 g_womh[NEXP*FDIM*DMODEL], g_woml[NEXP*FDIM*DMODEL];

__device__ __forceinline__ void split1(float v, bf16& h, bf16& l) {
    h = __float2bfloat16(v);
    l = __float2bfloat16(v - __bfloat162float(h));
}

// ---------------- flat vectorized split ----------------
__global__ void split4_k(const float* __restrict__ src, bf16* __restrict__ hi,
                         bf16* __restrict__ lo, long long n)
{
    long long i = ((long long)blockIdx.x * blockDim.x + threadIdx.x) * 4;
    if (i >= n) return;
    float4 v = *(const float4*)&src[i];
    bf16 h0,l0,h1,l1,h2,l2,h3,l3;
    split1(v.x,h0,l0); split1(v.y,h1,l1); split1(v.z,h2,l2); split1(v.w,h3,l3);
    hi[i]=h0; hi[i+1]=h1; hi[i+2]=h2; hi[i+3]=h3;
    lo[i]=l0; lo[i+1]=l1; lo[i+2]=l2; lo[i+3]=l3;
}

// ---------------- split with column offset (qkv weight concat) ----------------
__global__ void split_off_k(const float* __restrict__ src, bf16* __restrict__ hi,
                            bf16* __restrict__ lo, int ncol, int dstStride,
                            int colOff, long long total)
{
    long long i = (long long)blockIdx.x * blockDim.x + threadIdx.x;
    if (i >= total) return;
    int kr = (int)(i / ncol);
    int n  = (int)(i % ncol);
    bf16 h, l; split1(src[i], h, l);
    long long d = (long long)kr * dstStride + colOff + n;
    hi[d] = h; lo[d] = l;
}

// ---------------- RMSNorm (+optional fp32 out, + hi/lo split out) ----------------
__global__ void rmsnorm_split_k(const float* __restrict__ x, const float* __restrict__ sc,
                                float* __restrict__ yf, bf16* __restrict__ yh,
                                bf16* __restrict__ yl)
{
    int row = blockIdx.x;
    int tid = threadIdx.x;
    const float* xr = x + (size_t)row * DMODEL;
    float ss = 0.f;
    for (int d = tid; d < DMODEL; d += 256) { float v = xr[d]; ss += v * v; }
    __shared__ float red[256];
    red[tid] = ss; __syncthreads();
    for (int st = 128; st > 0; st >>= 1) {
        if (tid < st) red[tid] += red[tid + st];
        __syncthreads();
    }
    float inv = rsqrtf(red[0] / (float)DMODEL + 1e-6f);
    size_t base = (size_t)row * DMODEL;
    for (int d = tid; d < DMODEL; d += 256) {
        float v = xr[d] * inv * sc[d];
        if (yf) yf[base + d] = v;
        bf16 h, l; split1(v, h, l);
        yh[base + d] = h; yl[base + d] = l;
    }
}

// ================= bf16x3 tensor-core GEMM =================
// BM=128,BN=128,BK=32; 8 warps, warp tile 64x32; mma.m16n8k16.bf16 x3 terms.
#define ASTR 40    // bf16 per A smem row (80B)
#define BSTR 136   // bf16 per B smem row (272B)
#define OFF_AH(s) ((s)*5120)
#define OFF_AL(s) (10240 + (s)*5120)
#define OFF_BH(s) (20480 + (s)*4352)
#define OFF_BL(s) (29184 + (s)*4352)
#define SMEM_GEMM_BYTES (37888*2)

__device__ __forceinline__ void ldm_x4(uint32_t* r, uint32_t addr) {
    asm volatile("ldmatrix.sync.aligned.m8n8.x4.shared.b16 {%0,%1,%2,%3}, [%4];"
        : "=r"(r[0]), "=r"(r[1]), "=r"(r[2]), "=r"(r[3]) : "r"(addr));
}
__device__ __forceinline__ void ldm_x2t(uint32_t* r, uint32_t addr) {
    asm volatile("ldmatrix.sync.aligned.m8n8.x2.trans.shared.b16 {%0,%1}, [%2];"
        : "=r"(r[0]), "=r"(r[1]) : "r"(addr));
}
__device__ __forceinline__ void mma_bf16(float* c, const uint32_t* a, const uint32_t* b) {
    asm volatile(
        "mma.sync.aligned.m16n8k16.row.col.f32.bf16.bf16.f32 "
        "{%0,%1,%2,%3}, {%4,%5,%6,%7}, {%8,%9}, {%0,%1,%2,%3};"
        : "+f"(c[0]), "+f"(c[1]), "+f"(c[2]), "+f"(c[3])
        : "r"(a[0]), "r"(a[1]), "r"(a[2]), "r"(a[3]), "r"(b[0]), "r"(b[1]));
}
__device__ __forceinline__ void cp16(uint32_t dst, const void* src) {
    asm volatile("cp.async.cg.shared.global [%0], [%1], 16;" :: "r"(dst), "l"(src));
}
__device__ __forceinline__ void cp16_zero(uint32_t dst, const void* src) {
    asm volatile("cp.async.cg.shared.global [%0], [%1], 16, 0;" :: "r"(dst), "l"(src));
}

__global__ __launch_bounds__(256, 1)
void bf16_gemm_k(const bf16* __restrict__ Ah, const bf16* __restrict__ Al,
                 const bf16* __restrict__ Bhg, const bf16* __restrict__ Blg,
                 const float* __restrict__ res, float* __restrict__ C,
                 int M, int N, int K,
                 const int* __restrict__ perm,
                 const int* __restrict__ cnts, const int* __restrict__ offs,
                 long long strideB)
{
    extern __shared__ bf16 sm[];
    int rowBase = 0;
    const bf16* Bh = Bhg;
    const bf16* Bl = Blg;
    if (cnts) {
        int e = blockIdx.z;
        M = cnts[e];
        rowBase = offs[e];
        Bh = Bhg + (long long)e * strideB;
        Bl = Blg + (long long)e * strideB;
    }
    int bm = blockIdx.y * 128;
    if (bm >= M) return;
    int bn = blockIdx.x * 128;

    int tid  = threadIdx.x;
    int lane = tid & 31;
    int w    = tid >> 5;
    int wm   = w & 1;
    int wn   = w >> 1;

    uint32_t smBase = (uint32_t)__cvta_generic_to_shared(sm);
    uint32_t aLane  = ((lane & 15) * ASTR + (lane >> 4) * 8) * 2;
    uint32_t bLane  = ((lane & 15) * BSTR) * 2;

    // A load coords: one row per thread, 32B (2 chunks) per component
    int rA  = tid >> 1;
    int ac0 = (tid & 1) * 16;               // bf16 elems
    int aIdx = -1;
    if (bm + rA < M) { int r = rowBase + bm + rA; aIdx = perm ? perm[r] : r; }

    // B load coords: row rB, two 8-elem chunks
    int rB  = tid >> 3;                     // 0..31
    int bc0 = (tid & 7) * 8;                // 0..56

    float acc[4][4][4];
#pragma unroll
    for (int i = 0; i < 4; i++)
#pragma unroll
        for (int j = 0; j < 4; j++)
#pragma unroll
            for (int c = 0; c < 4; c++) acc[i][j][c] = 0.f;

    const int NKT = K >> 5;

    auto prefetch = [&](int kt, int st) {
        int k0 = kt << 5;
        // A hi/lo
        uint32_t dAh = smBase + (OFF_AH(st) + rA * ASTR + ac0) * 2;
        uint32_t dAl = smBase + (OFF_AL(st) + rA * ASTR + ac0) * 2;
        if (aIdx >= 0) {
            const bf16* sh = Ah + (size_t)aIdx * K + k0 + ac0;
            const bf16* sl = Al + (size_t)aIdx * K + k0 + ac0;
            cp16(dAh, sh);      cp16(dAh + 16, sh + 8);
            cp16(dAl, sl);      cp16(dAl + 16, sl + 8);
        } else {
            cp16_zero(dAh, Ah); cp16_zero(dAh + 16, Ah);
            cp16_zero(dAl, Al); cp16_zero(dAl + 16, Al);
        }
        // B hi/lo
        uint32_t dBh = smBase + (OFF_BH(st) + rB * BSTR + bc0) * 2;
        uint32_t dBl = smBase + (OFF_BL(st) + rB * BSTR + bc0) * 2;
        const bf16* sbh = Bh + (size_t)(k0 + rB) * N + bn + bc0;
        const bf16* sbl = Bl + (size_t)(k0 + rB) * N + bn + bc0;
        cp16(dBh, sbh);       cp16(dBh + 128, sbh + 64);
        cp16(dBl, sbl);       cp16(dBl + 128, sbl + 64);
    };

    prefetch(0, 0);
    asm volatile("cp.async.commit_group;" ::: "memory");

    for (int kt = 0; kt < NKT; kt++) {
        int st = kt & 1;
        if (kt + 1 < NKT) {
            prefetch(kt + 1, st ^ 1);
            asm volatile("cp.async.commit_group;" ::: "memory");
            asm volatile("cp.async.wait_group 1;" ::: "memory");
        } else {
            asm volatile("cp.async.wait_group 0;" ::: "memory");
        }
        __syncthreads();

        uint32_t aBaseH = smBase + (OFF_AH(st) + wm * 64 * ASTR) * 2 + aLane;
        uint32_t aBaseL = smBase + (OFF_AL(st) + wm * 64 * ASTR) * 2 + aLane;
        uint32_t bBaseH = smBase + (OFF_BH(st)) * 2 + wn * 32 * 2 + bLane;
        uint32_t bBaseL = smBase + (OFF_BL(st)) * 2 + wn * 32 * 2 + bLane;

#pragma unroll
        for (int ks = 0; ks < 2; ks++) {
            uint32_t ah[4][4], al[4][4];
#pragma unroll
            for (int mf = 0; mf < 4; mf++) {
                uint32_t off = mf * (16 * ASTR * 2) + ks * 32;
                ldm_x4(ah[mf], aBaseH + off);
                ldm_x4(al[mf], aBaseL + off);
            }
            uint32_t bh[4][2], bl[4][2];
#pragma unroll
            for (int nf = 0; nf < 4; nf++) {
                uint32_t off = nf * 16 + ks * (16 * BSTR * 2);
                ldm_x2t(bh[nf], bBaseH + off);
                ldm_x2t(bl[nf], bBaseL + off);
            }
#pragma unroll
            for (int mf = 0; mf < 4; mf++)
#pragma unroll
                for (int nf = 0; nf < 4; nf++)
                    mma_bf16(acc[mf][nf], ah[mf], bh[nf]);
#pragma unroll
            for (int mf = 0; mf < 4; mf++)
#pragma unroll
                for (int nf = 0; nf < 4; nf++)
                    mma_bf16(acc[mf][nf], ah[mf], bl[nf]);
#pragma unroll
            for (int mf = 0; mf < 4; mf++)
#pragma unroll
                for (int nf = 0; nf < 4; nf++)
                    mma_bf16(acc[mf][nf], al[mf], bh[nf]);
        }
        __syncthreads();
    }

    int g   = lane >> 2;
    int tig = lane & 3;
#pragma unroll
    for (int mf = 0; mf < 4; mf++) {
        int row0 = bm + wm * 64 + mf * 16 + g;
        int row1 = row0 + 8;
#pragma unroll
        for (int nf = 0; nf < 4; nf++) {
            int col = bn + wn * 32 + nf * 8 + tig * 2;
            if (row0 < M) {
                size_t o = (size_t)(rowBase + row0) * N + col;
                float2 v = make_float2(acc[mf][nf][0], acc[mf][nf][1]);
                if (res) { float2 r = *(const float2*)&res[o]; v.x += r.x; v.y += r.y; }
                *(float2*)&C[o] = v;
            }
            if (row1 < M) {
                size_t o = (size_t)(rowBase + row1) * N + col;
                float2 v = make_float2(acc[mf][nf][2], acc[mf][nf][3]);
                if (res) { float2 r = *(const float2*)&res[o]; v.x += r.x; v.y += r.y; }
                *(float2*)&C[o] = v;
            }
        }
    }
}

// ---------------- RoPE (row-stride aware) ----------------
__global__ void rope_k(float* __restrict__ x, const int* __restrict__ pos,
                       int nheads, int rowStride, float scale, int total)
{
    int idx = blockIdx.x * blockDim.x + threadIdx.x;
    if (idx >= total) return;
    int i   = idx & 63;
    int th  = idx >> 6;
    int h   = th % nheads;
    int tok = th / nheads;
    float freq = powf(10000.0f, -(float)i / 64.0f);
    float ang = (float)pos[tok] * freq;
    float c = cosf(ang), s = sinf(ang);
    float* row = x + (size_t)tok * rowStride + h * HD;
    float x1 = row[i], x2 = row[i + 64];
    row[i]      = (x1 * c - x2 * s) * scale;
    row[i + 64] = (x2 * c + x1 * s) * scale;
}

// ---------------- flash attention (fp32) -> ctx hi/lo ----------------
#define QT 32
#define KT 32
#define PADW 132

__global__ void flash_k(const float* __restrict__ Q, const float* __restrict__ Kg,
                        const float* __restrict__ Vg, const int* __restrict__ seg,
                        bf16* __restrict__ Oh, bf16* __restrict__ Ol)
{
    extern __shared__ float sh[];
    float* Qs = sh;
    float* Ks = Qs + QT * PADW;
    float* Vs = Ks + KT * PADW;
    float* Sc = Vs + KT * PADW;
    float* Mr = Sc + QT * KT;
    float* Lr = Mr + QT;
    float* Ar = Lr + QT;
    int*   Sq = (int*)(Ar + QT);
    int*   Sk = Sq + QT;

    int tid = threadIdx.x;
    int q0  = blockIdx.x * QT;
    int h   = blockIdx.y;
    int b   = blockIdx.z;
    int tok0 = b * S_LEN;
    int hk  = h >> 1;

    for (int idx = tid; idx < QT * HD; idx += 256) {
        int r = idx >> 7, d = idx & 127;
        Qs[r * PADW + d] = Q[(size_t)(tok0 + q0 + r) * QKVN + h * HD + d];
    }
    if (tid < QT) { Sq[tid] = seg[tok0 + q0 + tid]; Mr[tid] = -3.0e38f; Lr[tid] = 0.f; }

    float4 o[4];
#pragma unroll
    for (int c = 0; c < 4; c++) o[c] = make_float4(0.f, 0.f, 0.f, 0.f);
    int i = tid >> 3;
    int dbase = (tid & 7) * 16;

    int ktend = (q0 + QT - 1) / KT;
    for (int kt = 0; kt <= ktend; kt++) {
        int k0 = kt * KT;
        __syncthreads();
        for (int idx = tid; idx < KT * HD; idx += 256) {
            int r = idx >> 7, d = idx & 127;
            size_t gg = (size_t)(tok0 + k0 + r) * QKVN + hk * HD + d;
            Ks[r * PADW + d] = Kg[gg];
            Vs[r * PADW + d] = Vg[gg];
        }
        if (tid < KT) Sk[tid] = seg[tok0 + k0 + tid];
        __syncthreads();

        {
            int si = tid >> 3;
            int jbase = (tid & 7) * 4;
            const float4* qp = (const float4*)(Qs + si * PADW);
#pragma unroll
            for (int jj = 0; jj < 4; jj++) {
                int j = jbase + jj;
                int qi = q0 + si, kj = k0 + j;
                float sval;
                if (kj > qi || Sq[si] != Sk[j]) {
                    sval = -1e9f;
                } else {
                    const float4* kp = (const float4*)(Ks + j * PADW);
                    float a0 = 0.f;
#pragma unroll
                    for (int d4 = 0; d4 < 32; d4++) {
                        float4 av = qp[d4], cv = kp[d4];
                        a0 += av.x * cv.x + av.y * cv.y + av.z * cv.z + av.w * cv.w;
                    }
                    sval = a0;
                }
                Sc[si * KT + j] = sval;
            }
        }
        __syncthreads();

        if (tid < QT) {
            int r = tid;
            float mo = Mr[r], mx = mo;
#pragma unroll
            for (int j = 0; j < KT; j++) mx = fmaxf(mx, Sc[r * KT + j]);
            float al = expf(mo - mx);
            float ls = 0.f;
#pragma unroll
            for (int j = 0; j < KT; j++) {
                float p = expf(Sc[r * KT + j] - mx);
                Sc[r * KT + j] = p;
                ls += p;
            }
            Mr[r] = mx;
            Lr[r] = Lr[r] * al + ls;
            Ar[r] = al;
        }
        __syncthreads();

        {
            float al = Ar[i];
#pragma unroll
            for (int c = 0; c < 4; c++) { o[c].x *= al; o[c].y *= al; o[c].z *= al; o[c].w *= al; }
#pragma unroll
            for (int j = 0; j < KT; j++) {
                float p = Sc[i * KT + j];
                const float4* vp = (const float4*)(Vs + j * PADW + dbase);
#pragma unroll
                for (int c = 0; c < 4; c++) {
                    float4 v = vp[c];
                    o[c].x += p * v.x; o[c].y += p * v.y; o[c].z += p * v.z; o[c].w += p * v.w;
                }
            }
        }
    }

    float linv = 1.0f / Lr[i];
    size_t obase = (size_t)(tok0 + q0 + i) * DMODEL + h * HD + dbase;
#pragma unroll
    for (int c = 0; c < 4; c++) {
        float4 v = o[c];
        float vals[4] = { v.x * linv, v.y * linv, v.z * linv, v.w * linv };
#pragma unroll
        for (int e = 0; e < 4; e++) {
            bf16 hh, ll; split1(vals[e], hh, ll);
            Oh[obase + c * 4 + e] = hh;
            Ol[obase + c * 4 + e] = ll;
        }
    }
}

// ---------------- gating ----------------
__global__ void gate_k(const float* __restrict__ h, const float* __restrict__ gw,
                       int* __restrict__ tope, float* __restrict__ wgt)
{
    int tok = blockIdx.x;
    int tid = threadIdx.x;
    float s[NEXP];
#pragma unroll
    for (int e = 0; e < NEXP; e++) s[e] = 0.f;
    const float* hr = h + (size_t)tok * DMODEL;
    for (int d = tid; d < DMODEL; d += 128) {
        float hv = hr[d];
#pragma unroll
        for (int e = 0; e < NEXP; e++) s[e] += hv * gw[d * NEXP + e];
    }
    __shared__ float red[NEXP][128];
#pragma unroll
    for (int e = 0; e < NEXP; e++) red[e][tid] = s[e];
    __syncthreads();
    for (int st = 64; st > 0; st >>= 1) {
        if (tid < st)
#pragma unroll
            for (int e = 0; e < NEXP; e++) red[e][tid] += red[e][tid + st];
        __syncthreads();
    }
    if (tid == 0) {
        float l[NEXP];
#pragma unroll
        for (int e = 0; e < NEXP; e++) l[e] = red[e][0];
        int i0 = 0;
#pragma unroll
        for (int e = 1; e < NEXP; e++) if (l[e] > l[i0]) i0 = e;
        int i1 = -1;
#pragma unroll
        for (int e = 0; e < NEXP; e++)
            if (e != i0 && (i1 < 0 || l[e] > l[i1])) i1 = e;
        float z = expf(l[i1] - l[i0]);
        float w0 = 1.0f / (1.0f + z);
        tope[tok * 2]     = i0;  wgt[tok * 2]     = w0;
        tope[tok * 2 + 1] = i1;  wgt[tok * 2 + 1] = 1.0f - w0;
    }
}

// ---------------- bucketize ----------------
__global__ void bucketize_k()
{
    __shared__ int sc[NEXP], cur[NEXP];
    int tid = threadIdx.x;
    if (tid < NEXP) sc[tid] = 0;
    __syncthreads();
    for (int a = tid; a < NASSIGN; a += 256) atomicAdd(&sc[g_tope[a]], 1);
    __syncthreads();
    if (tid == 0) {
        int o = 0;
        for (int e = 0; e < NEXP; e++) {
            g_cnt[e] = sc[e]; g_off[e] = o; cur[e] = o; o += sc[e];
        }
    }
    __syncthreads();
    for (int a = tid; a < NASSIGN; a += 256) {
        int e = g_tope[a];
        int p = atomicAdd(&cur[e], 1);
        g_perm[p] = a >> 1;
        g_slot[a] = p;
    }
}

// ---------------- SiLU(a0)*a1 -> hi/lo ----------------
__global__ void silu_mul_k(int total)
{
    int idx = blockIdx.x * blockDim.x + threadIdx.x;
    if (idx >= total) return;
    float a = g_act0[idx];
    float b = g_act1[idx];
    float v = (a / (1.0f + expf(-a))) * b;
    bf16 h, l; split1(v, h, l);
    g_acth[idx] = h; g_actl[idx] = l;
}

// ---------------- combine ----------------
__global__ void combine_k(float* __restrict__ out, int total)
{
    int idx = blockIdx.x * blockDim.x + threadIdx.x;
    if (idx >= total) return;
    int tok = idx >> 11;
    int d   = idx & 2047;
    int s0 = g_slot[tok * 2],     s1 = g_slot[tok * 2 + 1];
    float w0 = g_wgt[tok * 2],    w1 = g_wgt[tok * 2 + 1];
    out[idx] = g_inter[idx]
             + w0 * g_eout[(size_t)s0 * DMODEL + d]
             + w1 * g_eout[(size_t)s1 * DMODEL + d];
}

// =============================== launcher ===============================
extern "C" void kernel_launch(void* const* d_in, const int* in_sizes, int n_in,
                              void* d_out, int out_size)
{
    const float* inputs  = (const float*)d_in[0];
    const float* pre_s   = (const float*)d_in[1];
    const float* post_s  = (const float*)d_in[2];
    const float* wq      = (const float*)d_in[3];
    const float* wk      = (const float*)d_in[4];
    const float* wv      = (const float*)d_in[5];
    const float* wo_attn = (const float*)d_in[6];
    const float* gate_w  = (const float*)d_in[7];
    const float* wi0     = (const float*)d_in[8];
    const float* wi1     = (const float*)d_in[9];
    const float* wo_mlp  = (const float*)d_in[10];
    const int*   seg     = (const int*)d_in[11];
    const int*   pos     = (const int*)d_in[12];
    float* out = (float*)d_out;

    float *qkv, *inter, *h, *act0, *act1, *eout, *wgt;
    int *perm, *slot, *tope, *cnt, *off;
    bf16 *lnxh,*lnxl,*cth,*ctl,*hh,*hl,*acth,*actl;
    bf16 *qkvwh,*qkvwl,*woh,*wol,*wi0h,*wi0l,*wi1h,*wi1l,*womh,*woml;
    cudaGetSymbolAddress((void**)&qkv,  g_qkv);
    cudaGetSymbolAddress((void**)&inter,g_inter);
    cudaGetSymbolAddress((void**)&h,    g_hbuf);
    cudaGetSymbolAddress((void**)&act0, g_act0);
    cudaGetSymbolAddress((void**)&act1, g_act1);
    cudaGetSymbolAddress((void**)&eout, g_eout);
    cudaGetSymbolAddress((void**)&perm, g_perm);
    cudaGetSymbolAddress((void**)&slot, g_slot);
    cudaGetSymbolAddress((void**)&tope, g_tope);
    cudaGetSymbolAddress((void**)&wgt,  g_wgt);
    cudaGetSymbolAddress((void**)&cnt,  g_cnt);
    cudaGetSymbolAddress((void**)&off,  g_off);
    cudaGetSymbolAddress((void**)&lnxh, g_lnxh);
    cudaGetSymbolAddress((void**)&lnxl, g_lnxl);
    cudaGetSymbolAddress((void**)&cth,  g_cth);
    cudaGetSymbolAddress((void**)&ctl,  g_ctl);
    cudaGetSymbolAddress((void**)&hh,   g_hh);
    cudaGetSymbolAddress((void**)&hl,   g_hl);
    cudaGetSymbolAddress((void**)&acth, g_acth);
    cudaGetSymbolAddress((void**)&actl, g_actl);
    cudaGetSymbolAddress((void**)&qkvwh,g_qkvwh);
    cudaGetSymbolAddress((void**)&qkvwl,g_qkvwl);
    cudaGetSymbolAddress((void**)&woh,  g_woh);
    cudaGetSymbolAddress((void**)&wol,  g_wol);
    cudaGetSymbolAddress((void**)&wi0h, g_wi0h);
    cudaGetSymbolAddress((void**)&wi0l, g_wi0l);
    cudaGetSymbolAddress((void**)&wi1h, g_wi1h);
    cudaGetSymbolAddress((void**)&wi1l, g_wi1l);
    cudaGetSymbolAddress((void**)&womh, g_womh);
    cudaGetSymbolAddress((void**)&woml, g_woml);

    const size_t FLASH_SMEM = (size_t)(3 * QT * PADW + QT * KT + 3 * QT) * sizeof(float)
                            + (size_t)(QT + KT) * sizeof(int);
    cudaFuncSetAttribute(flash_k, cudaFuncAttributeMaxDynamicSharedMemorySize,
                         (int)FLASH_SMEM);
    cudaFuncSetAttribute(bf16_gemm_k, cudaFuncAttributeMaxDynamicSharedMemorySize,
                         SMEM_GEMM_BYTES);

    // 0) weight splits
    {
        long long t;
        t = (long long)DMODEL * DMODEL;
        split_off_k<<<(int)((t + 255) / 256), 256>>>(wq, qkvwh, qkvwl, DMODEL, QKVN, 0, t);
        t = (long long)DMODEL * (HKVN * HD);
        split_off_k<<<(int)((t + 255) / 256), 256>>>(wk, qkvwh, qkvwl, HKVN * HD, QKVN, 2048, t);
        split_off_k<<<(int)((t + 255) / 256), 256>>>(wv, qkvwh, qkvwl, HKVN * HD, QKVN, 3072, t);
        t = (long long)DMODEL * DMODEL;
        split4_k<<<(int)((t / 4 + 255) / 256), 256>>>(wo_attn, woh, wol, t);
        t = (long long)NEXP * DMODEL * FDIM;
        split4_k<<<(int)((t / 4 + 255) / 256), 256>>>(wi0, wi0h, wi0l, t);
        split4_k<<<(int)((t / 4 + 255) / 256), 256>>>(wi1, wi1h, wi1l, t);
        split4_k<<<(int)((t / 4 + 255) / 256), 256>>>(wo_mlp, womh, woml, t);
    }

    // 1) pre-attention RMSNorm -> lnx hi/lo
    rmsnorm_split_k<<<NT, 256>>>(inputs, pre_s, nullptr, lnxh, lnxl);

    // 2) fused QKV projection -> qkv[NT][4096]
    bf16_gemm_k<<<dim3(QKVN/128, NT/128, 1), 256, SMEM_GEMM_BYTES>>>(
        lnxh, lnxl, qkvwh, qkvwl, nullptr, qkv,
        NT, QKVN, DMODEL, nullptr, nullptr, nullptr, 0);

    // 3) RoPE
    {
        int totq = NT * HQN * 64;
        rope_k<<<(totq + 255) / 256, 256>>>(qkv, pos, HQN, QKVN, 0.08838834764831845f, totq);
        int totk = NT * HKVN * 64;
        rope_k<<<(totk + 255) / 256, 256>>>(qkv + 2048, pos, HKVN, QKVN, 1.0f, totk);
    }

    // 4) flash attention -> ctx hi/lo
    flash_k<<<dim3(S_LEN/QT, HQN, BATCH), 256, FLASH_SMEM>>>(
        qkv, qkv + 2048, qkv + 3072, seg, cth, ctl);

    // 5) O projection + residual -> inter
    bf16_gemm_k<<<dim3(DMODEL/128, NT/128, 1), 256, SMEM_GEMM_BYTES>>>(
        cth, ctl, woh, wol, inputs, inter,
        NT, DMODEL, DMODEL, nullptr, nullptr, nullptr, 0);

    // 6) post-attention RMSNorm -> h fp32 + hi/lo
    rmsnorm_split_k<<<NT, 256>>>(inter, post_s, h, hh, hl);

    // 7) gating
    gate_k<<<NT, 128>>>(h, gate_w, tope, wgt);

    // 8) bucketize
    bucketize_k<<<1, 256>>>();

    // 9) MoE up-projections
    bf16_gemm_k<<<dim3(FDIM/128, NASSIGN/128, NEXP), 256, SMEM_GEMM_BYTES>>>(
        hh, hl, wi0h, wi0l, nullptr, act0,
        0, FDIM, DMODEL, perm, cnt, off, (long long)DMODEL * FDIM);
    bf16_gemm_k<<<dim3(FDIM/128, NASSIGN/128, NEXP), 256, SMEM_GEMM_BYTES>>>(
        hh, hl, wi1h, wi1l, nullptr, act1,
        0, FDIM, DMODEL, perm, cnt, off, (long long)DMODEL * FDIM);

    // 10) SiLU * mul -> act hi/lo
    silu_mul_k<<<(NASSIGN * FDIM) / 256, 256>>>(NASSIGN * FDIM);

    // 11) MoE down-projection
    bf16_gemm_k<<<dim3(DMODEL/128, NASSIGN/128, NEXP), 256, SMEM_GEMM_BYTES>>>(
        acth, actl, womh, woml, nullptr, eout,
        0, DMODEL, FDIM, nullptr, cnt, off, (long long)FDIM * DMODEL);

    // 12) combine
    combine_k<<<(NT * DMODEL) / 256, 256>>>(out, NT * DMODEL);
}

// round 4
// speedup vs baseline: 3.4904x; 2.3519x over previous
#include <cuda_runtime.h>
#include <cuda_bf16.h>
#include <cstdint>
#include <math.h>

#define NT      4096       // B*S tokens
#define DMODEL  2048
#define S_LEN   2048
#define BATCH   2
#define HQN     16
#define HKVN    8
#define HD      128
#define NEXP    8
#define FDIM    4096
#define NASSIGN (NT*2)
#define QKVN    4096       // 2048 q + 1024 k + 1024 v

typedef __nv_bfloat16 bf16;

// ---------------- scratch ----------------
__device__ float g_qkv [NT*QKVN];
__device__ float g_inter[NT*DMODEL];
__device__ float g_hbuf[NT*DMODEL];
__device__ float g_act0[NASSIGN*FDIM];
__device__ float g_act1[NASSIGN*FDIM];
__device__ float g_eout[NASSIGN*DMODEL];
__device__ int   g_perm[NASSIGN];
__device__ int   g_slot[NASSIGN];
__device__ int   g_tope[NASSIGN];
__device__ float g_wgt [NASSIGN];
__device__ int   g_cnt [NEXP];
__device__ int   g_off [NEXP];

// bf16 hi/lo operand arrays
__device__ bf16 g_lnxh[NT*DMODEL],  g_lnxl[NT*DMODEL];
__device__ bf16 g_cth [NT*DMODEL],  g_ctl [NT*DMODEL];
__device__ bf16 g_hh  [NT*DMODEL],  g_hl  [NT*DMODEL];
__device__ bf16 g_acth[NASSIGN*FDIM], g_actl[NASSIGN*FDIM];
__device__ bf16 g_qkvwh[DMODEL*QKVN], g_qkvwl[DMODEL*QKVN];
__device__ bf16 g_woh [DMODEL*DMODEL], g_wol [DMODEL*DMODEL];
__device__ bf16 g_wi0h[NEXP*DMODEL*FDIM], g_wi0l[NEXP*DMODEL*FDIM];
__device__ bf16 g_wi1h[NEXP*DMODEL*FDIM], g_wi1l[NEXP*DMODEL*FDIM];
__device__ bf16 g_womh[NEXP*FDIM*DMODEL], g_woml[NEXP*FDIM*DMODEL];
// attention operands (hi/lo)
__device__ bf16 g_qh[NT*HQN*HD], g_ql[NT*HQN*HD];
__device__ bf16 g_kh[NT*HKVN*HD], g_kl[NT*HKVN*HD];
__device__ bf16 g_vh[NT*HKVN*HD], g_vl[NT*HKVN*HD];

__device__ __forceinline__ void split1(float v, bf16& h, bf16& l) {
    h = __float2bfloat16(v);
    l = __float2bfloat16(v - __bfloat162float(h));
}
__device__ __forceinline__ uint32_t packbf2(bf16 a, bf16 b) {
    __nv_bfloat162 p; p.x = a; p.y = b;
    return *(uint32_t*)&p;
}

// ---------------- flat vectorized split ----------------
__global__ void split4_k(const float* __restrict__ src, bf16* __restrict__ hi,
                         bf16* __restrict__ lo, long long n)
{
    long long i = ((long long)blockIdx.x * blockDim.x + threadIdx.x) * 4;
    if (i >= n) return;
    float4 v = *(const float4*)&src[i];
    bf16 h0,l0,h1,l1,h2,l2,h3,l3;
    split1(v.x,h0,l0); split1(v.y,h1,l1); split1(v.z,h2,l2); split1(v.w,h3,l3);
    hi[i]=h0; hi[i+1]=h1; hi[i+2]=h2; hi[i+3]=h3;
    lo[i]=l0; lo[i+1]=l1; lo[i+2]=l2; lo[i+3]=l3;
}

// ---------------- split with column offset (qkv weight concat) ----------------
__global__ void split_off_k(const float* __restrict__ src, bf16* __restrict__ hi,
                            bf16* __restrict__ lo, int ncol, int dstStride,
                            int colOff, long long total)
{
    long long i = (long long)blockIdx.x * blockDim.x + threadIdx.x;
    if (i >= total) return;
    int kr = (int)(i / ncol);
    int n  = (int)(i % ncol);
    bf16 h, l; split1(src[i], h, l);
    long long d = (long long)kr * dstStride + colOff + n;
    hi[d] = h; lo[d] = l;
}

// ---------------- RMSNorm (+optional fp32 out, + hi/lo split out) ----------------
__global__ void rmsnorm_split_k(const float* __restrict__ x, const float* __restrict__ sc,
                                float* __restrict__ yf, bf16* __restrict__ yh,
                                bf16* __restrict__ yl)
{
    int row = blockIdx.x;
    int tid = threadIdx.x;
    const float* xr = x + (size_t)row * DMODEL;
    float ss = 0.f;
    for (int d = tid; d < DMODEL; d += 256) { float v = xr[d]; ss += v * v; }
    __shared__ float red[256];
    red[tid] = ss; __syncthreads();
    for (int st = 128; st > 0; st >>= 1) {
        if (tid < st) red[tid] += red[tid + st];
        __syncthreads();
    }
    float inv = rsqrtf(red[0] / (float)DMODEL + 1e-6f);
    size_t base = (size_t)row * DMODEL;
    for (int d = tid; d < DMODEL; d += 256) {
        float v = xr[d] * inv * sc[d];
        if (yf) yf[base + d] = v;
        bf16 h, l; split1(v, h, l);
        yh[base + d] = h; yl[base + d] = l;
    }
}

// ================= bf16x3 tensor-core GEMM =================
#define ASTR 40
#define BSTR 136
#define OFF_AH(s) ((s)*5120)
#define OFF_AL(s) (10240 + (s)*5120)
#define OFF_BH(s) (20480 + (s)*4352)
#define OFF_BL(s) (29184 + (s)*4352)
#define SMEM_GEMM_BYTES (37888*2)

__device__ __forceinline__ void ldm_x4(uint32_t* r, uint32_t addr) {
    asm volatile("ldmatrix.sync.aligned.m8n8.x4.shared.b16 {%0,%1,%2,%3}, [%4];"
        : "=r"(r[0]), "=r"(r[1]), "=r"(r[2]), "=r"(r[3]) : "r"(addr));
}
__device__ __forceinline__ void ldm_x2t(uint32_t* r, uint32_t addr) {
    asm volatile("ldmatrix.sync.aligned.m8n8.x2.trans.shared.b16 {%0,%1}, [%2];"
        : "=r"(r[0]), "=r"(r[1]) : "r"(addr));
}
__device__ __forceinline__ void mma_bf16(float* c, const uint32_t* a, const uint32_t* b) {
    asm volatile(
        "mma.sync.aligned.m16n8k16.row.col.f32.bf16.bf16.f32 "
        "{%0,%1,%2,%3}, {%4,%5,%6,%7}, {%8,%9}, {%0,%1,%2,%3};"
        : "+f"(c[0]), "+f"(c[1]), "+f"(c[2]), "+f"(c[3])
        : "r"(a[0]), "r"(a[1]), "r"(a[2]), "r"(a[3]), "r"(b[0]), "r"(b[1]));
}
__device__ __forceinline__ void cp16(uint32_t dst, const void* src) {
    asm volatile("cp.async.cg.shared.global [%0], [%1], 16;" :: "r"(dst), "l"(src));
}
__device__ __forceinline__ void cp16_zero(uint32_t dst, const void* src) {
    asm volatile("cp.async.cg.shared.global [%0], [%1], 16, 0;" :: "r"(dst), "l"(src));
}

__global__ __launch_bounds__(256, 1)
void bf16_gemm_k(const bf16* __restrict__ Ah, const bf16* __restrict__ Al,
                 const bf16* __restrict__ Bhg, const bf16* __restrict__ Blg,
                 const float* __restrict__ res, float* __restrict__ C,
                 int M, int N, int K,
                 const int* __restrict__ perm,
                 const int* __restrict__ cnts, const int* __restrict__ offs,
                 long long strideB)
{
    extern __shared__ bf16 sm[];
    int rowBase = 0;
    const bf16* Bh = Bhg;
    const bf16* Bl = Blg;
    if (cnts) {
        int e = blockIdx.z;
        M = cnts[e];
        rowBase = offs[e];
        Bh = Bhg + (long long)e * strideB;
        Bl = Blg + (long long)e * strideB;
    }
    int bm = blockIdx.y * 128;
    if (bm >= M) return;
    int bn = blockIdx.x * 128;

    int tid  = threadIdx.x;
    int lane = tid & 31;
    int w    = tid >> 5;
    int wm   = w & 1;
    int wn   = w >> 1;

    uint32_t smBase = (uint32_t)__cvta_generic_to_shared(sm);
    uint32_t aLane  = ((lane & 15) * ASTR + (lane >> 4) * 8) * 2;
    uint32_t bLane  = ((lane & 15) * BSTR) * 2;

    int rA  = tid >> 1;
    int ac0 = (tid & 1) * 16;
    int aIdx = -1;
    if (bm + rA < M) { int r = rowBase + bm + rA; aIdx = perm ? perm[r] : r; }

    int rB  = tid >> 3;
    int bc0 = (tid & 7) * 8;

    float acc[4][4][4];
#pragma unroll
    for (int i = 0; i < 4; i++)
#pragma unroll
        for (int j = 0; j < 4; j++)
#pragma unroll
            for (int c = 0; c < 4; c++) acc[i][j][c] = 0.f;

    const int NKT = K >> 5;

    auto prefetch = [&](int kt, int st) {
        int k0 = kt << 5;
        uint32_t dAh = smBase + (OFF_AH(st) + rA * ASTR + ac0) * 2;
        uint32_t dAl = smBase + (OFF_AL(st) + rA * ASTR + ac0) * 2;
        if (aIdx >= 0) {
            const bf16* sh = Ah + (size_t)aIdx * K + k0 + ac0;
            const bf16* sl = Al + (size_t)aIdx * K + k0 + ac0;
            cp16(dAh, sh);      cp16(dAh + 16, sh + 8);
            cp16(dAl, sl);      cp16(dAl + 16, sl + 8);
        } else {
            cp16_zero(dAh, Ah); cp16_zero(dAh + 16, Ah);
            cp16_zero(dAl, Al); cp16_zero(dAl + 16, Al);
        }
        uint32_t dBh = smBase + (OFF_BH(st) + rB * BSTR + bc0) * 2;
        uint32_t dBl = smBase + (OFF_BL(st) + rB * BSTR + bc0) * 2;
        const bf16* sbh = Bh + (size_t)(k0 + rB) * N + bn + bc0;
        const bf16* sbl = Bl + (size_t)(k0 + rB) * N + bn + bc0;
        cp16(dBh, sbh);       cp16(dBh + 128, sbh + 64);
        cp16(dBl, sbl);       cp16(dBl + 128, sbl + 64);
    };

    prefetch(0, 0);
    asm volatile("cp.async.commit_group;" ::: "memory");

    for (int kt = 0; kt < NKT; kt++) {
        int st = kt & 1;
        if (kt + 1 < NKT) {
            prefetch(kt + 1, st ^ 1);
            asm volatile("cp.async.commit_group;" ::: "memory");
            asm volatile("cp.async.wait_group 1;" ::: "memory");
        } else {
            asm volatile("cp.async.wait_group 0;" ::: "memory");
        }
        __syncthreads();

        uint32_t aBaseH = smBase + (OFF_AH(st) + wm * 64 * ASTR) * 2 + aLane;
        uint32_t aBaseL = smBase + (OFF_AL(st) + wm * 64 * ASTR) * 2 + aLane;
        uint32_t bBaseH = smBase + (OFF_BH(st)) * 2 + wn * 32 * 2 + bLane;
        uint32_t bBaseL = smBase + (OFF_BL(st)) * 2 + wn * 32 * 2 + bLane;

#pragma unroll
        for (int ks = 0; ks < 2; ks++) {
            uint32_t ah[4][4], al[4][4];
#pragma unroll
            for (int mf = 0; mf < 4; mf++) {
                uint32_t off = mf * (16 * ASTR * 2) + ks * 32;
                ldm_x4(ah[mf], aBaseH + off);
                ldm_x4(al[mf], aBaseL + off);
            }
            uint32_t bh[4][2], bl[4][2];
#pragma unroll
            for (int nf = 0; nf < 4; nf++) {
                uint32_t off = nf * 16 + ks * (16 * BSTR * 2);
                ldm_x2t(bh[nf], bBaseH + off);
                ldm_x2t(bl[nf], bBaseL + off);
            }
#pragma unroll
            for (int mf = 0; mf < 4; mf++)
#pragma unroll
                for (int nf = 0; nf < 4; nf++)
                    mma_bf16(acc[mf][nf], ah[mf], bh[nf]);
#pragma unroll
            for (int mf = 0; mf < 4; mf++)
#pragma unroll
                for (int nf = 0; nf < 4; nf++)
                    mma_bf16(acc[mf][nf], ah[mf], bl[nf]);
#pragma unroll
            for (int mf = 0; mf < 4; mf++)
#pragma unroll
                for (int nf = 0; nf < 4; nf++)
                    mma_bf16(acc[mf][nf], al[mf], bh[nf]);
        }
        __syncthreads();
    }

    int g   = lane >> 2;
    int tig = lane & 3;
#pragma unroll
    for (int mf = 0; mf < 4; mf++) {
        int row0 = bm + wm * 64 + mf * 16 + g;
        int row1 = row0 + 8;
#pragma unroll
        for (int nf = 0; nf < 4; nf++) {
            int col = bn + wn * 32 + nf * 8 + tig * 2;
            if (row0 < M) {
                size_t o = (size_t)(rowBase + row0) * N + col;
                float2 v = make_float2(acc[mf][nf][0], acc[mf][nf][1]);
                if (res) { float2 r = *(const float2*)&res[o]; v.x += r.x; v.y += r.y; }
                *(float2*)&C[o] = v;
            }
            if (row1 < M) {
                size_t o = (size_t)(rowBase + row1) * N + col;
                float2 v = make_float2(acc[mf][nf][2], acc[mf][nf][3]);
                if (res) { float2 r = *(const float2*)&res[o]; v.x += r.x; v.y += r.y; }
                *(float2*)&C[o] = v;
            }
        }
    }
}

// ---------------- RoPE + hi/lo split (q or k section of qkv buffer) ------------
__global__ void rope_split_k(const float* __restrict__ qkv, const int* __restrict__ pos,
                             int srcOff, int nheads, float scale,
                             bf16* __restrict__ outH, bf16* __restrict__ outL, int total)
{
    int idx = blockIdx.x * blockDim.x + threadIdx.x;
    if (idx >= total) return;
    int i   = idx & 63;
    int th  = idx >> 6;
    int h   = th % nheads;
    int tok = th / nheads;
    float freq = powf(10000.0f, -(float)i / 64.0f);
    float ang = (float)pos[tok] * freq;
    float c = cosf(ang), s = sinf(ang);
    const float* row = qkv + (size_t)tok * QKVN + srcOff + h * HD;
    float x1 = row[i], x2 = row[i + 64];
    float y1 = (x1 * c - x2 * s) * scale;
    float y2 = (x2 * c + x1 * s) * scale;
    size_t o = (size_t)tok * (nheads * HD) + h * HD;
    bf16 hh, ll;
    split1(y1, hh, ll); outH[o + i] = hh;      outL[o + i] = ll;
    split1(y2, hh, ll); outH[o + i + 64] = hh; outL[o + i + 64] = ll;
}

// ---------------- V hi/lo split ----------------
__global__ void splitv_k(const float* __restrict__ qkv,
                         bf16* __restrict__ vh, bf16* __restrict__ vl, int total)
{
    int idx = blockIdx.x * blockDim.x + threadIdx.x;
    if (idx >= total) return;
    int tok = idx >> 10;
    int d   = idx & 1023;
    float v = qkv[(size_t)tok * QKVN + 3072 + d];
    bf16 h, l; split1(v, h, l);
    vh[idx] = h; vl[idx] = l;
}

// ================= tensor-core flash attention =================
// QT=64, KT=32, 4 warps, warp owns 16 q rows; bf16x3 for QK^T and P*V.
#define FQT 64
#define FKT 32
#define FSTR 136
#define F_QH 0
#define F_QL 8704
#define F_KH(s) (17408 + (s)*4352)
#define F_KL(s) (26112 + (s)*4352)
#define F_VH(s) (34816 + (s)*4352)
#define F_VL(s) (43520 + (s)*4352)
#define FLASH_SMEM_BYTES (52224*2)

__global__ __launch_bounds__(128)
void flash2_k(const bf16* __restrict__ Qh, const bf16* __restrict__ Ql,
              const bf16* __restrict__ Kh, const bf16* __restrict__ Kl,
              const bf16* __restrict__ Vh, const bf16* __restrict__ Vl,
              const int* __restrict__ seg,
              bf16* __restrict__ Oh, bf16* __restrict__ Ol)
{
    extern __shared__ bf16 fsm[];
    __shared__ int Sq[FQT];
    __shared__ int Sk[2][FKT];

    int tid  = threadIdx.x;
    int lane = tid & 31;
    int w    = tid >> 5;
    int g    = lane >> 2;
    int tig  = lane & 3;

    int q0  = blockIdx.x * FQT;
    int h   = blockIdx.y;
    int b   = blockIdx.z;
    int tok0 = b * S_LEN;
    int hk  = h >> 1;

    uint32_t smBase = (uint32_t)__cvta_generic_to_shared(fsm);

    // ---- Q tile load (cp.async) ----
    {
        int r  = tid >> 1;
        int c0 = (tid & 1) * 64;
        const bf16* sqh = Qh + (size_t)(tok0 + q0 + r) * (HQN * HD) + h * HD + c0;
        const bf16* sql = Ql + (size_t)(tok0 + q0 + r) * (HQN * HD) + h * HD + c0;
        uint32_t dh = smBase + (F_QH + r * FSTR + c0) * 2;
        uint32_t dl = smBase + (F_QL + r * FSTR + c0) * 2;
#pragma unroll
        for (int j = 0; j < 8; j++) {
            cp16(dh + j * 16, sqh + j * 8);
            cp16(dl + j * 16, sql + j * 8);
        }
    }
    if (tid < FQT) Sq[tid] = seg[tok0 + q0 + tid];

    auto prefetch = [&](int kt, int st) {
        int k0 = kt * FKT;
        int r  = tid >> 2;
        int c0 = (tid & 3) * 32;
        size_t gbase = (size_t)(tok0 + k0 + r) * (HKVN * HD) + hk * HD + c0;
        uint32_t dkh = smBase + (F_KH(st) + r * FSTR + c0) * 2;
        uint32_t dkl = smBase + (F_KL(st) + r * FSTR + c0) * 2;
        uint32_t dvh = smBase + (F_VH(st) + r * FSTR + c0) * 2;
        uint32_t dvl = smBase + (F_VL(st) + r * FSTR + c0) * 2;
#pragma unroll
        for (int j = 0; j < 4; j++) {
            cp16(dkh + j * 16, Kh + gbase + j * 8);
            cp16(dkl + j * 16, Kl + gbase + j * 8);
            cp16(dvh + j * 16, Vh + gbase + j * 8);
            cp16(dvl + j * 16, Vl + gbase + j * 8);
        }
        if (tid < FKT) Sk[st][tid] = seg[tok0 + k0 + tid];
    };

    prefetch(0, 0);
    asm volatile("cp.async.commit_group;" ::: "memory");

    float of[16][4];
#pragma unroll
    for (int nf = 0; nf < 16; nf++)
#pragma unroll
        for (int c = 0; c < 4; c++) of[nf][c] = 0.f;
    float m0 = -1e9f, m1 = -1e9f, l0 = 0.f, l1 = 0.f;

    // precomputed lane addresses
    uint32_t qAddrH = smBase + (F_QH + (w * 16 + (lane & 15)) * FSTR + (lane >> 4) * 8) * 2;
    uint32_t qAddrL = qAddrH + (F_QL - F_QH) * 2;
    int ktokoff = (lane & 7) + ((lane >> 4) << 3);
    int kdhalf  = ((lane >> 3) & 1) * 8;
    int vrow    = lane & 15;

    int ktend = (q0 + FQT - 1) / FKT;
    int myrow0 = q0 + w * 16 + g;
    int myrow1 = myrow0 + 8;
    int sq0 = Sq[0], sq1 = Sq[0];   // placeholder; real read after sync below

    for (int kt = 0; kt <= ktend; kt++) {
        int st = kt & 1;
        if (kt + 1 <= ktend) {
            prefetch(kt + 1, st ^ 1);
            asm volatile("cp.async.commit_group;" ::: "memory");
            asm volatile("cp.async.wait_group 1;" ::: "memory");
        } else {
            asm volatile("cp.async.wait_group 0;" ::: "memory");
        }
        __syncthreads();
        if (kt == 0) { sq0 = Sq[w * 16 + g]; sq1 = Sq[w * 16 + g + 8]; }
        int k0 = kt * FKT;

        // ---- S = Q K^T (bf16 x3) ----
        float sf[4][4];
#pragma unroll
        for (int nf = 0; nf < 4; nf++)
#pragma unroll
            for (int c = 0; c < 4; c++) sf[nf][c] = 0.f;

        uint32_t kBaseH = smBase + (F_KH(st) + ktokoff * FSTR + kdhalf) * 2;
        uint32_t kBaseL = smBase + (F_KL(st) + ktokoff * FSTR + kdhalf) * 2;

#pragma unroll
        for (int kk = 0; kk < 8; kk++) {
            uint32_t qh[4], ql[4];
            ldm_x4(qh, qAddrH + kk * 32);
            ldm_x4(ql, qAddrL + kk * 32);
#pragma unroll
            for (int p = 0; p < 2; p++) {
                uint32_t kh4[4], kl4[4];
                uint32_t off = (p * 16 * FSTR + kk * 16) * 2;
                ldm_x4(kh4, kBaseH + off);
                ldm_x4(kl4, kBaseL + off);
                mma_bf16(sf[2 * p],     qh, kh4);
                mma_bf16(sf[2 * p],     qh, kl4);
                mma_bf16(sf[2 * p],     ql, kh4);
                mma_bf16(sf[2 * p + 1], qh, kh4 + 2);
                mma_bf16(sf[2 * p + 1], qh, kl4 + 2);
                mma_bf16(sf[2 * p + 1], ql, kh4 + 2);
            }
        }

        // ---- mask + online softmax ----
#pragma unroll
        for (int nf = 0; nf < 4; nf++) {
            int c0g = k0 + nf * 8 + 2 * tig;
            int sk0 = Sk[st][nf * 8 + 2 * tig];
            int sk1 = Sk[st][nf * 8 + 2 * tig + 1];
            if (c0g > myrow0     || sk0 != sq0) sf[nf][0] = -1e9f;
            if (c0g + 1 > myrow0 || sk1 != sq0) sf[nf][1] = -1e9f;
            if (c0g > myrow1     || sk0 != sq1) sf[nf][2] = -1e9f;
            if (c0g + 1 > myrow1 || sk1 != sq1) sf[nf][3] = -1e9f;
        }
        float mx0 = -1e9f, mx1 = -1e9f;
#pragma unroll
        for (int nf = 0; nf < 4; nf++) {
            mx0 = fmaxf(mx0, fmaxf(sf[nf][0], sf[nf][1]));
            mx1 = fmaxf(mx1, fmaxf(sf[nf][2], sf[nf][3]));
        }
        mx0 = fmaxf(mx0, __shfl_xor_sync(0xffffffff, mx0, 1));
        mx0 = fmaxf(mx0, __shfl_xor_sync(0xffffffff, mx0, 2));
        mx1 = fmaxf(mx1, __shfl_xor_sync(0xffffffff, mx1, 1));
        mx1 = fmaxf(mx1, __shfl_xor_sync(0xffffffff, mx1, 2));
        float mn0 = fmaxf(m0, mx0), mn1 = fmaxf(m1, mx1);
        float al0 = __expf(m0 - mn0), al1 = __expf(m1 - mn1);
        m0 = mn0; m1 = mn1;
        float ls0 = 0.f, ls1 = 0.f;
#pragma unroll
        for (int nf = 0; nf < 4; nf++) {
            sf[nf][0] = __expf(sf[nf][0] - mn0);
            sf[nf][1] = __expf(sf[nf][1] - mn0);
            sf[nf][2] = __expf(sf[nf][2] - mn1);
            sf[nf][3] = __expf(sf[nf][3] - mn1);
            ls0 += sf[nf][0] + sf[nf][1];
            ls1 += sf[nf][2] + sf[nf][3];
        }
        l0 = l0 * al0 + ls0;
        l1 = l1 * al1 + ls1;
#pragma unroll
        for (int nf = 0; nf < 16; nf++) {
            of[nf][0] *= al0; of[nf][1] *= al0;
            of[nf][2] *= al1; of[nf][3] *= al1;
        }

        // ---- O += P V (bf16 x3) ----
        uint32_t vBaseH = smBase + (F_VH(st) + vrow * FSTR) * 2;
        uint32_t vBaseL = smBase + (F_VL(st) + vrow * FSTR) * 2;
#pragma unroll
        for (int t = 0; t < 2; t++) {
            uint32_t pah[4], pal[4];
#pragma unroll
            for (int q = 0; q < 2; q++) {
                float p0 = sf[2 * t + q][0], p1 = sf[2 * t + q][1];
                float p2 = sf[2 * t + q][2], p3 = sf[2 * t + q][3];
                bf16 h0, e0, h1, e1, h2, e2, h3, e3;
                split1(p0, h0, e0); split1(p1, h1, e1);
                split1(p2, h2, e2); split1(p3, h3, e3);
                pah[2 * q]     = packbf2(h0, h1);
                pal[2 * q]     = packbf2(e0, e1);
                pah[2 * q + 1] = packbf2(h2, h3);
                pal[2 * q + 1] = packbf2(e2, e3);
            }
#pragma unroll
            for (int nf = 0; nf < 16; nf++) {
                uint32_t vh2[2], vl2[2];
                uint32_t off = (t * 16 * FSTR + nf * 8) * 2;
                ldm_x2t(vh2, vBaseH + off);
                ldm_x2t(vl2, vBaseL + off);
                mma_bf16(of[nf], pah, vh2);
                mma_bf16(of[nf], pah, vl2);
                mma_bf16(of[nf], pal, vh2);
            }
        }
        __syncthreads();
    }

    // ---- epilogue ----
    l0 += __shfl_xor_sync(0xffffffff, l0, 1);
    l0 += __shfl_xor_sync(0xffffffff, l0, 2);
    l1 += __shfl_xor_sync(0xffffffff, l1, 1);
    l1 += __shfl_xor_sync(0xffffffff, l1, 2);
    float i0 = 1.0f / l0, i1 = 1.0f / l1;
    size_t r0 = (size_t)(tok0 + myrow0) * DMODEL + h * HD;
    size_t r1 = (size_t)(tok0 + myrow1) * DMODEL + h * HD;
#pragma unroll
    for (int nf = 0; nf < 16; nf++) {
        int col = nf * 8 + 2 * tig;
        bf16 h0, e0, h1, e1;
        split1(of[nf][0] * i0, h0, e0); split1(of[nf][1] * i0, h1, e1);
        *(uint32_t*)&Oh[r0 + col] = packbf2(h0, h1);
        *(uint32_t*)&Ol[r0 + col] = packbf2(e0, e1);
        split1(of[nf][2] * i1, h0, e0); split1(of[nf][3] * i1, h1, e1);
        *(uint32_t*)&Oh[r1 + col] = packbf2(h0, h1);
        *(uint32_t*)&Ol[r1 + col] = packbf2(e0, e1);
    }
}

// ---------------- gating ----------------
__global__ void gate_k(const float* __restrict__ h, const float* __restrict__ gw,
                       int* __restrict__ tope, float* __restrict__ wgt)
{
    int tok = blockIdx.x;
    int tid = threadIdx.x;
    float s[NEXP];
#pragma unroll
    for (int e = 0; e < NEXP; e++) s[e] = 0.f;
    const float* hr = h + (size_t)tok * DMODEL;
    for (int d = tid; d < DMODEL; d += 128) {
        float hv = hr[d];
#pragma unroll
        for (int e = 0; e < NEXP; e++) s[e] += hv * gw[d * NEXP + e];
    }
    __shared__ float red[NEXP][128];
#pragma unroll
    for (int e = 0; e < NEXP; e++) red[e][tid] = s[e];
    __syncthreads();
    for (int st = 64; st > 0; st >>= 1) {
        if (tid < st)
#pragma unroll
            for (int e = 0; e < NEXP; e++) red[e][tid] += red[e][tid + st];
        __syncthreads();
    }
    if (tid == 0) {
        float l[NEXP];
#pragma unroll
        for (int e = 0; e < NEXP; e++) l[e] = red[e][0];
        int i0 = 0;
#pragma unroll
        for (int e = 1; e < NEXP; e++) if (l[e] > l[i0]) i0 = e;
        int i1 = -1;
#pragma unroll
        for (int e = 0; e < NEXP; e++)
            if (e != i0 && (i1 < 0 || l[e] > l[i1])) i1 = e;
        float z = expf(l[i1] - l[i0]);
        float w0 = 1.0f / (1.0f + z);
        tope[tok * 2]     = i0;  wgt[tok * 2]     = w0;
        tope[tok * 2 + 1] = i1;  wgt[tok * 2 + 1] = 1.0f - w0;
    }
}

// ---------------- bucketize ----------------
__global__ void bucketize_k()
{
    __shared__ int sc[NEXP], cur[NEXP];
    int tid = threadIdx.x;
    if (tid < NEXP) sc[tid] = 0;
    __syncthreads();
    for (int a = tid; a < NASSIGN; a += 256) atomicAdd(&sc[g_tope[a]], 1);
    __syncthreads();
    if (tid == 0) {
        int o = 0;
        for (int e = 0; e < NEXP; e++) {
            g_cnt[e] = sc[e]; g_off[e] = o; cur[e] = o; o += sc[e];
        }
    }
    __syncthreads();
    for (int a = tid; a < NASSIGN; a += 256) {
        int e = g_tope[a];
        int p = atomicAdd(&cur[e], 1);
        g_perm[p] = a >> 1;
        g_slot[a] = p;
    }
}

// ---------------- SiLU(a0)*a1 -> hi/lo ----------------
__global__ void silu_mul_k(int total)
{
    int idx = blockIdx.x * blockDim.x + threadIdx.x;
    if (idx >= total) return;
    float a = g_act0[idx];
    float b = g_act1[idx];
    float v = (a / (1.0f + expf(-a))) * b;
    bf16 h, l; split1(v, h, l);
    g_acth[idx] = h; g_actl[idx] = l;
}

// ---------------- combine ----------------
__global__ void combine_k(float* __restrict__ out, int total)
{
    int idx = blockIdx.x * blockDim.x + threadIdx.x;
    if (idx >= total) return;
    int tok = idx >> 11;
    int d   = idx & 2047;
    int s0 = g_slot[tok * 2],     s1 = g_slot[tok * 2 + 1];
    float w0 = g_wgt[tok * 2],    w1 = g_wgt[tok * 2 + 1];
    out[idx] = g_inter[idx]
             + w0 * g_eout[(size_t)s0 * DMODEL + d]
             + w1 * g_eout[(size_t)s1 * DMODEL + d];
}

// =============================== launcher ===============================
extern "C" void kernel_launch(void* const* d_in, const int* in_sizes, int n_in,
                              void* d_out, int out_size)
{
    const float* inputs  = (const float*)d_in[0];
    const float* pre_s   = (const float*)d_in[1];
    const float* post_s  = (const float*)d_in[2];
    const float* wq      = (const float*)d_in[3];
    const float* wk      = (const float*)d_in[4];
    const float* wv      = (const float*)d_in[5];
    const float* wo_attn = (const float*)d_in[6];
    const float* gate_w  = (const float*)d_in[7];
    const float* wi0     = (const float*)d_in[8];
    const float* wi1     = (const float*)d_in[9];
    const float* wo_mlp  = (const float*)d_in[10];
    const int*   seg     = (const int*)d_in[11];
    const int*   pos     = (const int*)d_in[12];
    float* out = (float*)d_out;

    float *qkv, *inter, *h, *act0, *act1, *eout, *wgt;
    int *perm, *slot, *tope, *cnt, *off;
    bf16 *lnxh,*lnxl,*cth,*ctl,*hh,*hl,*acth,*actl;
    bf16 *qkvwh,*qkvwl,*woh,*wol,*wi0h,*wi0l,*wi1h,*wi1l,*womh,*woml;
    bf16 *qh,*ql,*kh,*kl,*vh,*vl;
    cudaGetSymbolAddress((void**)&qkv,  g_qkv);
    cudaGetSymbolAddress((void**)&inter,g_inter);
    cudaGetSymbolAddress((void**)&h,    g_hbuf);
    cudaGetSymbolAddress((void**)&act0, g_act0);
    cudaGetSymbolAddress((void**)&act1, g_act1);
    cudaGetSymbolAddress((void**)&eout, g_eout);
    cudaGetSymbolAddress((void**)&perm, g_perm);
    cudaGetSymbolAddress((void**)&slot, g_slot);
    cudaGetSymbolAddress((void**)&tope, g_tope);
    cudaGetSymbolAddress((void**)&wgt,  g_wgt);
    cudaGetSymbolAddress((void**)&cnt,  g_cnt);
    cudaGetSymbolAddress((void**)&off,  g_off);
    cudaGetSymbolAddress((void**)&lnxh, g_lnxh);
    cudaGetSymbolAddress((void**)&lnxl, g_lnxl);
    cudaGetSymbolAddress((void**)&cth,  g_cth);
    cudaGetSymbolAddress((void**)&ctl,  g_ctl);
    cudaGetSymbolAddress((void**)&hh,   g_hh);
    cudaGetSymbolAddress((void**)&hl,   g_hl);
    cudaGetSymbolAddress((void**)&acth, g_acth);
    cudaGetSymbolAddress((void**)&actl, g_actl);
    cudaGetSymbolAddress((void**)&qkvwh,g_qkvwh);
    cudaGetSymbolAddress((void**)&qkvwl,g_qkvwl);
    cudaGetSymbolAddress((void**)&woh,  g_woh);
    cudaGetSymbolAddress((void**)&wol,  g_wol);
    cudaGetSymbolAddress((void**)&wi0h, g_wi0h);
    cudaGetSymbolAddress((void**)&wi0l, g_wi0l);
    cudaGetSymbolAddress((void**)&wi1h, g_wi1h);
    cudaGetSymbolAddress((void**)&wi1l, g_wi1l);
    cudaGetSymbolAddress((void**)&womh, g_womh);
    cudaGetSymbolAddress((void**)&woml, g_woml);
    cudaGetSymbolAddress((void**)&qh,   g_qh);
    cudaGetSymbolAddress((void**)&ql,   g_ql);
    cudaGetSymbolAddress((void**)&kh,   g_kh);
    cudaGetSymbolAddress((void**)&kl,   g_kl);
    cudaGetSymbolAddress((void**)&vh,   g_vh);
    cudaGetSymbolAddress((void**)&vl,   g_vl);

    cudaFuncSetAttribute(bf16_gemm_k, cudaFuncAttributeMaxDynamicSharedMemorySize,
                         SMEM_GEMM_BYTES);
    cudaFuncSetAttribute(flash2_k, cudaFuncAttributeMaxDynamicSharedMemorySize,
                         FLASH_SMEM_BYTES);

    // 0) weight splits
    {
        long long t;
        t = (long long)DMODEL * DMODEL;
        split_off_k<<<(int)((t + 255) / 256), 256>>>(wq, qkvwh, qkvwl, DMODEL, QKVN, 0, t);
        t = (long long)DMODEL * (HKVN * HD);
        split_off_k<<<(int)((t + 255) / 256), 256>>>(wk, qkvwh, qkvwl, HKVN * HD, QKVN, 2048, t);
        split_off_k<<<(int)((t + 255) / 256), 256>>>(wv, qkvwh, qkvwl, HKVN * HD, QKVN, 3072, t);
        t = (long long)DMODEL * DMODEL;
        split4_k<<<(int)((t / 4 + 255) / 256), 256>>>(wo_attn, woh, wol, t);
        t = (long long)NEXP * DMODEL * FDIM;
        split4_k<<<(int)((t / 4 + 255) / 256), 256>>>(wi0, wi0h, wi0l, t);
        split4_k<<<(int)((t / 4 + 255) / 256), 256>>>(wi1, wi1h, wi1l, t);
        split4_k<<<(int)((t / 4 + 255) / 256), 256>>>(wo_mlp, womh, woml, t);
    }

    // 1) pre-attention RMSNorm -> lnx hi/lo
    rmsnorm_split_k<<<NT, 256>>>(inputs, pre_s, nullptr, lnxh, lnxl);

    // 2) fused QKV projection -> qkv fp32
    bf16_gemm_k<<<dim3(QKVN/128, NT/128, 1), 256, SMEM_GEMM_BYTES>>>(
        lnxh, lnxl, qkvwh, qkvwl, nullptr, qkv,
        NT, QKVN, DMODEL, nullptr, nullptr, nullptr, 0);

    // 3) RoPE + hi/lo split of q, k; split v
    {
        int totq = NT * HQN * 64;
        rope_split_k<<<(totq + 255) / 256, 256>>>(qkv, pos, 0, HQN,
            0.08838834764831845f, qh, ql, totq);
        int totk = NT * HKVN * 64;
        rope_split_k<<<(totk + 255) / 256, 256>>>(qkv, pos, 2048, HKVN,
            1.0f, kh, kl, totk);
        int totv = NT * HKVN * HD;
        splitv_k<<<(totv + 255) / 256, 256>>>(qkv, vh, vl, totv);
    }

    // 4) tensor-core flash attention -> ctx hi/lo
    flash2_k<<<dim3(S_LEN/FQT, HQN, BATCH), 128, FLASH_SMEM_BYTES>>>(
        qh, ql, kh, kl, vh, vl, seg, cth, ctl);

    // 5) O projection + residual -> inter
    bf16_gemm_k<<<dim3(DMODEL/128, NT/128, 1), 256, SMEM_GEMM_BYTES>>>(
        cth, ctl, woh, wol, inputs, inter,
        NT, DMODEL, DMODEL, nullptr, nullptr, nullptr, 0);

    // 6) post-attention RMSNorm -> h fp32 + hi/lo
    rmsnorm_split_k<<<NT, 256>>>(inter, post_s, h, hh, hl);

    // 7) gating
    gate_k<<<NT, 128>>>(h, gate_w, tope, wgt);

    // 8) bucketize
    bucketize_k<<<1, 256>>>();

    // 9) MoE up-projections
    bf16_gemm_k<<<dim3(FDIM/128, NASSIGN/128, NEXP), 256, SMEM_GEMM_BYTES>>>(
        hh, hl, wi0h, wi0l, nullptr, act0,
        0, FDIM, DMODEL, perm, cnt, off, (long long)DMODEL * FDIM);
    bf16_gemm_k<<<dim3(FDIM/128, NASSIGN/128, NEXP), 256, SMEM_GEMM_BYTES>>>(
        hh, hl, wi1h, wi1l, nullptr, act1,
        0, FDIM, DMODEL, perm, cnt, off, (long long)DMODEL * FDIM);

    // 10) SiLU * mul -> act hi/lo
    silu_mul_k<<<(NASSIGN * FDIM) / 256, 256>>>(NASSIGN * FDIM);

    // 11) MoE down-projection
    bf16_gemm_k<<<dim3(DMODEL/128, NASSIGN/128, NEXP), 256, SMEM_GEMM_BYTES>>>(
        acth, actl, womh, woml, nullptr, eout,
        0, DMODEL, FDIM, nullptr, cnt, off, (long long)FDIM * DMODEL);

    // 12) combine
    combine_k<<<(NT * DMODEL) / 256, 256>>>(out, NT * DMODEL);
}

// round 6
// speedup vs baseline: 4.3242x; 1.2389x over previous
#include <cuda_runtime.h>
#include <cuda_fp16.h>
#include <cstdint>
#include <math.h>

#define NT      4096       // B*S tokens
#define DMODEL  2048
#define S_LEN   2048
#define BATCH   2
#define HQN     16
#define HKVN    8
#define HD      128
#define NEXP    8
#define FDIM    4096
#define NASSIGN (NT*2)
#define QKVN    4096       // 2048 q + 1024 k + 1024 v

typedef __half fp16;

// ---------------- scratch ----------------
__device__ float g_qkv [NT*QKVN];
__device__ float g_inter[NT*DMODEL];
__device__ float g_hbuf[NT*DMODEL];
__device__ float g_eout[NASSIGN*DMODEL];
__device__ int   g_perm[NASSIGN];
__device__ int   g_slot[NASSIGN];
__device__ int   g_tope[NASSIGN];
__device__ float g_wgt [NASSIGN];
__device__ int   g_cnt [NEXP];
__device__ int   g_off [NEXP];

// fp16 hi/lo activation planes
__device__ fp16 g_lnxh[NT*DMODEL],  g_lnxl[NT*DMODEL];
__device__ fp16 g_cth [NT*DMODEL],  g_ctl [NT*DMODEL];
__device__ fp16 g_hh  [NT*DMODEL],  g_hl  [NT*DMODEL];
__device__ fp16 g_acth[NASSIGN*FDIM], g_actl[NASSIGN*FDIM];
// fp16 single-plane weights
__device__ fp16 g_qkvw[DMODEL*QKVN];
__device__ fp16 g_wo  [DMODEL*DMODEL];
__device__ fp16 g_w01 [(size_t)NEXP*DMODEL*2*FDIM];   // interleaved wi0/wi1
__device__ fp16 g_wom [(size_t)NEXP*FDIM*DMODEL];
// attention operands
__device__ fp16 g_qh[NT*HQN*HD], g_ql[NT*HQN*HD];
__device__ fp16 g_kh[NT*HKVN*HD];
__device__ fp16 g_vh[NT*HKVN*HD];

__device__ __forceinline__ void split1h(float v, fp16& h, fp16& l) {
    h = __float2half(v);
    l = __float2half(v - __half2float(h));
}
__device__ __forceinline__ uint32_t packh2(fp16 a, fp16 b) {
    __half2 p; p.x = a; p.y = b;
    return *(uint32_t*)&p;
}
__device__ __forceinline__ void cp16(uint32_t dst, const void* src) {
    asm volatile("cp.async.cg.shared.global [%0], [%1], 16;" :: "r"(dst), "l"(src));
}
__device__ __forceinline__ void cp16_zero(uint32_t dst, const void* src) {
    asm volatile("cp.async.cg.shared.global [%0], [%1], 16, 0;" :: "r"(dst), "l"(src));
}
#define CP_COMMIT() asm volatile("cp.async.commit_group;" ::: "memory")

__device__ __forceinline__ void ldm_x4(uint32_t* r, uint32_t addr) {
    asm volatile("ldmatrix.sync.aligned.m8n8.x4.shared.b16 {%0,%1,%2,%3}, [%4];"
        : "=r"(r[0]), "=r"(r[1]), "=r"(r[2]), "=r"(r[3]) : "r"(addr));
}
__device__ __forceinline__ void ldm_x2t(uint32_t* r, uint32_t addr) {
    asm volatile("ldmatrix.sync.aligned.m8n8.x2.trans.shared.b16 {%0,%1}, [%2];"
        : "=r"(r[0]), "=r"(r[1]) : "r"(addr));
}
__device__ __forceinline__ void mma_f16(float* c, const uint32_t* a, const uint32_t* b) {
    asm volatile(
        "mma.sync.aligned.m16n8k16.row.col.f32.f16.f16.f32 "
        "{%0,%1,%2,%3}, {%4,%5,%6,%7}, {%8,%9}, {%0,%1,%2,%3};"
        : "+f"(c[0]), "+f"(c[1]), "+f"(c[2]), "+f"(c[3])
        : "r"(a[0]), "r"(a[1]), "r"(a[2]), "r"(a[3]), "r"(b[0]), "r"(b[1]));
}

// ---------------- weight convert (single fp16 plane, optional column interleave)
__global__ void wsplit_k(const float* __restrict__ src, fp16* __restrict__ dst,
                         int ncol, int dstStride, int colOff, int colMul,
                         long long srcZ, long long dstZ, long long total)
{
    long long i = (long long)blockIdx.x * blockDim.x + threadIdx.x;
    if (i >= total) return;
    int z = blockIdx.y;
    const float* s = src + (long long)z * srcZ;
    fp16* d = dst + (long long)z * dstZ;
    int kr = (int)(i / ncol);
    int n  = (int)(i % ncol);
    d[(long long)kr * dstStride + colOff + (long long)n * colMul] = __float2half(s[i]);
}

// ---------------- RMSNorm (+optional fp32 out, + hi/lo split out) ----------------
__global__ void rmsnorm_split_k(const float* __restrict__ x, const float* __restrict__ sc,
                                float* __restrict__ yf, fp16* __restrict__ yh,
                                fp16* __restrict__ yl)
{
    int row = blockIdx.x;
    int tid = threadIdx.x;
    const float* xr = x + (size_t)row * DMODEL;
    float ss = 0.f;
    for (int d = tid; d < DMODEL; d += 256) { float v = xr[d]; ss += v * v; }
    __shared__ float red[256];
    red[tid] = ss; __syncthreads();
    for (int st = 128; st > 0; st >>= 1) {
        if (tid < st) red[tid] += red[tid + st];
        __syncthreads();
    }
    float inv = rsqrtf(red[0] / (float)DMODEL + 1e-6f);
    size_t base = (size_t)row * DMODEL;
    for (int d = tid; d < DMODEL; d += 256) {
        float v = xr[d] * inv * sc[d];
        if (yf) yf[base + d] = v;
        fp16 h, l; split1h(v, h, l);
        yh[base + d] = h; yl[base + d] = l;
    }
}

// ================= fp16x2 tensor-core GEMM =================
// BM=128,BN=128,BK=32; 8 warps, warp tile 64x32; A split hi/lo, B single plane.
#define ASTR 40
#define BSTR 136
#define OFF_AH(s) ((s)*5120)
#define OFF_AL(s) (10240 + (s)*5120)
#define OFF_B(s)  (20480 + (s)*4352)
#define SMEM_GEMM_BYTES (29184*2)

__global__ __launch_bounds__(256, 1)
void fp16_gemm_k(const fp16* __restrict__ Ah, const fp16* __restrict__ Al,
                 const fp16* __restrict__ Bg,
                 const float* __restrict__ res, float* __restrict__ Cf,
                 fp16* __restrict__ SH, fp16* __restrict__ SL,
                 int M, int N, int K,
                 const int* __restrict__ perm,
                 const int* __restrict__ cnts, const int* __restrict__ offs,
                 long long strideB, int mode)
{
    extern __shared__ fp16 sm[];
    int rowBase = 0;
    const fp16* B = Bg;
    if (cnts) {
        int e = blockIdx.z;
        M = cnts[e];
        rowBase = offs[e];
        B = Bg + (long long)e * strideB;
    }
    int bm = blockIdx.y * 128;
    if (bm >= M) return;
    int bn = blockIdx.x * 128;

    int tid  = threadIdx.x;
    int lane = tid & 31;
    int w    = tid >> 5;
    int wm   = w & 1;
    int wn   = w >> 1;

    uint32_t smBase = (uint32_t)__cvta_generic_to_shared(sm);
    uint32_t aLane  = ((lane & 15) * ASTR + (lane >> 4) * 8) * 2;
    uint32_t bLane  = ((lane & 15) * BSTR) * 2;

    int rA  = tid >> 1;
    int ac0 = (tid & 1) * 16;
    int aIdx = -1;
    if (bm + rA < M) { int r = rowBase + bm + rA; aIdx = perm ? perm[r] : r; }

    int rB  = tid >> 3;
    int bc0 = (tid & 7) * 8;

    float acc[4][4][4];
#pragma unroll
    for (int i = 0; i < 4; i++)
#pragma unroll
        for (int j = 0; j < 4; j++)
#pragma unroll
            for (int c = 0; c < 4; c++) acc[i][j][c] = 0.f;

    const int NKT = K >> 5;

    auto prefetch = [&](int kt, int st) {
        int k0 = kt << 5;
        uint32_t dAh = smBase + (OFF_AH(st) + rA * ASTR + ac0) * 2;
        uint32_t dAl = smBase + (OFF_AL(st) + rA * ASTR + ac0) * 2;
        if (aIdx >= 0) {
            const fp16* sh = Ah + (size_t)aIdx * K + k0 + ac0;
            const fp16* sl = Al + (size_t)aIdx * K + k0 + ac0;
            cp16(dAh, sh);      cp16(dAh + 16, sh + 8);
            cp16(dAl, sl);      cp16(dAl + 16, sl + 8);
        } else {
            cp16_zero(dAh, Ah); cp16_zero(dAh + 16, Ah);
            cp16_zero(dAl, Al); cp16_zero(dAl + 16, Al);
        }
        uint32_t dB = smBase + (OFF_B(st) + rB * BSTR + bc0) * 2;
        const fp16* sb = B + (size_t)(k0 + rB) * N + bn + bc0;
        cp16(dB, sb);       cp16(dB + 128, sb + 64);
    };

    prefetch(0, 0);
    CP_COMMIT();

    for (int kt = 0; kt < NKT; kt++) {
        int st = kt & 1;
        if (kt + 1 < NKT) {
            prefetch(kt + 1, st ^ 1);
            CP_COMMIT();
            asm volatile("cp.async.wait_group 1;" ::: "memory");
        } else {
            asm volatile("cp.async.wait_group 0;" ::: "memory");
        }
        __syncthreads();

        uint32_t aBaseH = smBase + (OFF_AH(st) + wm * 64 * ASTR) * 2 + aLane;
        uint32_t aBaseL = smBase + (OFF_AL(st) + wm * 64 * ASTR) * 2 + aLane;
        uint32_t bBase  = smBase + (OFF_B(st)) * 2 + wn * 32 * 2 + bLane;

#pragma unroll
        for (int ks = 0; ks < 2; ks++) {
            uint32_t ah[4][4], al[4][4];
#pragma unroll
            for (int mf = 0; mf < 4; mf++) {
                uint32_t off = mf * (16 * ASTR * 2) + ks * 32;
                ldm_x4(ah[mf], aBaseH + off);
                ldm_x4(al[mf], aBaseL + off);
            }
            uint32_t bh[4][2];
#pragma unroll
            for (int nf = 0; nf < 4; nf++) {
                uint32_t off = nf * 16 + ks * (16 * BSTR * 2);
                ldm_x2t(bh[nf], bBase + off);
            }
#pragma unroll
            for (int mf = 0; mf < 4; mf++)
#pragma unroll
                for (int nf = 0; nf < 4; nf++)
                    mma_f16(acc[mf][nf], ah[mf], bh[nf]);
#pragma unroll
            for (int mf = 0; mf < 4; mf++)
#pragma unroll
                for (int nf = 0; nf < 4; nf++)
                    mma_f16(acc[mf][nf], al[mf], bh[nf]);
        }
        __syncthreads();
    }

    int g   = lane >> 2;
    int tig = lane & 3;
#pragma unroll
    for (int mf = 0; mf < 4; mf++) {
        int row0 = bm + wm * 64 + mf * 16 + g;
        int row1 = row0 + 8;
#pragma unroll
        for (int nf = 0; nf < 4; nf++) {
            int col = bn + wn * 32 + nf * 8 + tig * 2;
            if (mode == 0) {
                if (row0 < M) {
                    size_t o = (size_t)(rowBase + row0) * N + col;
                    float2 v = make_float2(acc[mf][nf][0], acc[mf][nf][1]);
                    if (res) { float2 r = *(const float2*)&res[o]; v.x += r.x; v.y += r.y; }
                    *(float2*)&Cf[o] = v;
                }
                if (row1 < M) {
                    size_t o = (size_t)(rowBase + row1) * N + col;
                    float2 v = make_float2(acc[mf][nf][2], acc[mf][nf][3]);
                    if (res) { float2 r = *(const float2*)&res[o]; v.x += r.x; v.y += r.y; }
                    *(float2*)&Cf[o] = v;
                }
            } else {
                // interleaved silu: even col = gate (wi0), odd col = value (wi1)
                int f = col >> 1;
                if (row0 < M) {
                    size_t o = (size_t)(rowBase + row0) * (size_t)(N >> 1) + f;
                    float a = acc[mf][nf][0], b = acc[mf][nf][1];
                    float v = (a / (1.0f + __expf(-a))) * b;
                    fp16 h, l; split1h(v, h, l);
                    SH[o] = h; SL[o] = l;
                }
                if (row1 < M) {
                    size_t o = (size_t)(rowBase + row1) * (size_t)(N >> 1) + f;
                    float a = acc[mf][nf][2], b = acc[mf][nf][3];
                    float v = (a / (1.0f + __expf(-a))) * b;
                    fp16 h, l; split1h(v, h, l);
                    SH[o] = h; SL[o] = l;
                }
            }
        }
    }
}

// ---------------- RoPE: q -> hi/lo planes ----------------
__global__ void rope_split_k(const float* __restrict__ qkv, const int* __restrict__ pos,
                             int srcOff, int nheads, float scale,
                             fp16* __restrict__ outH, fp16* __restrict__ outL, int total)
{
    int idx = blockIdx.x * blockDim.x + threadIdx.x;
    if (idx >= total) return;
    int i   = idx & 63;
    int th  = idx >> 6;
    int h   = th % nheads;
    int tok = th / nheads;
    float freq = powf(10000.0f, -(float)i / 64.0f);
    float ang = (float)pos[tok] * freq;
    float c = cosf(ang), s = sinf(ang);
    const float* row = qkv + (size_t)tok * QKVN + srcOff + h * HD;
    float x1 = row[i], x2 = row[i + 64];
    float y1 = (x1 * c - x2 * s) * scale;
    float y2 = (x2 * c + x1 * s) * scale;
    size_t o = (size_t)tok * (nheads * HD) + h * HD;
    fp16 hh, ll;
    split1h(y1, hh, ll); outH[o + i] = hh;      outL[o + i] = ll;
    split1h(y2, hh, ll); outH[o + i + 64] = hh; outL[o + i + 64] = ll;
}

// ---------------- RoPE: k -> single plane ----------------
__global__ void rope1_k(const float* __restrict__ qkv, const int* __restrict__ pos,
                        int srcOff, int nheads, fp16* __restrict__ outH, int total)
{
    int idx = blockIdx.x * blockDim.x + threadIdx.x;
    if (idx >= total) return;
    int i   = idx & 63;
    int th  = idx >> 6;
    int h   = th % nheads;
    int tok = th / nheads;
    float freq = powf(10000.0f, -(float)i / 64.0f);
    float ang = (float)pos[tok] * freq;
    float c = cosf(ang), s = sinf(ang);
    const float* row = qkv + (size_t)tok * QKVN + srcOff + h * HD;
    float x1 = row[i], x2 = row[i + 64];
    size_t o = (size_t)tok * (nheads * HD) + h * HD;
    outH[o + i]      = __float2half(x1 * c - x2 * s);
    outH[o + i + 64] = __float2half(x2 * c + x1 * s);
}

__global__ void splitv1_k(const float* __restrict__ qkv, fp16* __restrict__ vh, int total)
{
    int idx = blockIdx.x * blockDim.x + threadIdx.x;
    if (idx >= total) return;
    int tok = idx >> 10;
    int d   = idx & 1023;
    vh[idx] = __float2half(qkv[(size_t)tok * QKVN + 3072 + d]);
}

// ================= fp16x2 flash attention =================
// QT=64, KT=32, 4 warps; Q/P split hi/lo, K/V single plane.
#define FQT 64
#define FKT 32
#define FSTR 136
#define F_QH 0
#define F_QL 8704
#define F_K(s) (17408 + (s)*4352)
#define F_V(s) (26112 + (s)*4352)
#define FLASH_SMEM_BYTES (34816*2)

__global__ __launch_bounds__(128)
void flash2_k(const fp16* __restrict__ Qh, const fp16* __restrict__ Ql,
              const fp16* __restrict__ Kh, const fp16* __restrict__ Vh,
              const int* __restrict__ seg,
              fp16* __restrict__ Oh, fp16* __restrict__ Ol)
{
    extern __shared__ fp16 fsm[];
    __shared__ int Sq[FQT];
    __shared__ int Sk[2][FKT];

    int tid  = threadIdx.x;
    int lane = tid & 31;
    int w    = tid >> 5;
    int g    = lane >> 2;
    int tig  = lane & 3;

    int q0  = blockIdx.x * FQT;
    int h   = blockIdx.y;
    int b   = blockIdx.z;
    int tok0 = b * S_LEN;
    int hk  = h >> 1;

    uint32_t smBase = (uint32_t)__cvta_generic_to_shared(fsm);

    {
        int r  = tid >> 1;
        int c0 = (tid & 1) * 64;
        const fp16* sqh = Qh + (size_t)(tok0 + q0 + r) * (HQN * HD) + h * HD + c0;
        const fp16* sql = Ql + (size_t)(tok0 + q0 + r) * (HQN * HD) + h * HD + c0;
        uint32_t dh = smBase + (F_QH + r * FSTR + c0) * 2;
        uint32_t dl = smBase + (F_QL + r * FSTR + c0) * 2;
#pragma unroll
        for (int j = 0; j < 8; j++) {
            cp16(dh + j * 16, sqh + j * 8);
            cp16(dl + j * 16, sql + j * 8);
        }
    }
    if (tid < FQT) Sq[tid] = seg[tok0 + q0 + tid];

    auto prefetch = [&](int kt, int st) {
        int k0 = kt * FKT;
        int r  = tid >> 2;
        int c0 = (tid & 3) * 32;
        size_t gbase = (size_t)(tok0 + k0 + r) * (HKVN * HD) + hk * HD + c0;
        uint32_t dk = smBase + (F_K(st) + r * FSTR + c0) * 2;
        uint32_t dv = smBase + (F_V(st) + r * FSTR + c0) * 2;
#pragma unroll
        for (int j = 0; j < 4; j++) {
            cp16(dk + j * 16, Kh + gbase + j * 8);
            cp16(dv + j * 16, Vh + gbase + j * 8);
        }
        if (tid < FKT) Sk[st][tid] = seg[tok0 + k0 + tid];
    };

    prefetch(0, 0);
    CP_COMMIT();

    float of[16][4];
#pragma unroll
    for (int nf = 0; nf < 16; nf++)
#pragma unroll
        for (int c = 0; c < 4; c++) of[nf][c] = 0.f;
    float m0 = -1e9f, m1 = -1e9f, l0 = 0.f, l1 = 0.f;

    uint32_t qAddrH = smBase + (F_QH + (w * 16 + (lane & 15)) * FSTR + (lane >> 4) * 8) * 2;
    uint32_t qAddrL = qAddrH + (F_QL - F_QH) * 2;
    int ktokoff = (lane & 7) + ((lane >> 4) << 3);
    int kdhalf  = ((lane >> 3) & 1) * 8;
    int vrow    = lane & 15;

    int ktend = (q0 + FQT - 1) / FKT;
    int myrow0 = q0 + w * 16 + g;
    int myrow1 = myrow0 + 8;
    int sq0 = 0, sq1 = 0;

    for (int kt = 0; kt <= ktend; kt++) {
        int st = kt & 1;
        if (kt + 1 <= ktend) {
            prefetch(kt + 1, st ^ 1);
            CP_COMMIT();
            asm volatile("cp.async.wait_group 1;" ::: "memory");
        } else {
            asm volatile("cp.async.wait_group 0;" ::: "memory");
        }
        __syncthreads();
        if (kt == 0) { sq0 = Sq[w * 16 + g]; sq1 = Sq[w * 16 + g + 8]; }
        int k0 = kt * FKT;

        float sf[4][4];
#pragma unroll
        for (int nf = 0; nf < 4; nf++)
#pragma unroll
            for (int c = 0; c < 4; c++) sf[nf][c] = 0.f;

        uint32_t kBase = smBase + (F_K(st) + ktokoff * FSTR + kdhalf) * 2;

#pragma unroll
        for (int kk = 0; kk < 8; kk++) {
            uint32_t qh[4], ql[4];
            ldm_x4(qh, qAddrH + kk * 32);
            ldm_x4(ql, qAddrL + kk * 32);
#pragma unroll
            for (int p = 0; p < 2; p++) {
                uint32_t kh4[4];
                uint32_t off = (p * 16 * FSTR + kk * 16) * 2;
                ldm_x4(kh4, kBase + off);
                mma_f16(sf[2 * p],     qh, kh4);
                mma_f16(sf[2 * p],     ql, kh4);
                mma_f16(sf[2 * p + 1], qh, kh4 + 2);
                mma_f16(sf[2 * p + 1], ql, kh4 + 2);
            }
        }

#pragma unroll
        for (int nf = 0; nf < 4; nf++) {
            int c0g = k0 + nf * 8 + 2 * tig;
            int sk0 = Sk[st][nf * 8 + 2 * tig];
            int sk1 = Sk[st][nf * 8 + 2 * tig + 1];
            if (c0g > myrow0     || sk0 != sq0) sf[nf][0] = -1e9f;
            if (c0g + 1 > myrow0 || sk1 != sq0) sf[nf][1] = -1e9f;
            if (c0g > myrow1     || sk0 != sq1) sf[nf][2] = -1e9f;
            if (c0g + 1 > myrow1 || sk1 != sq1) sf[nf][3] = -1e9f;
        }
        float mx0 = -1e9f, mx1 = -1e9f;
#pragma unroll
        for (int nf = 0; nf < 4; nf++) {
            mx0 = fmaxf(mx0, fmaxf(sf[nf][0], sf[nf][1]));
            mx1 = fmaxf(mx1, fmaxf(sf[nf][2], sf[nf][3]));
        }
        mx0 = fmaxf(mx0, __shfl_xor_sync(0xffffffff, mx0, 1));
        mx0 = fmaxf(mx0, __shfl_xor_sync(0xffffffff, mx0, 2));
        mx1 = fmaxf(mx1, __shfl_xor_sync(0xffffffff, mx1, 1));
        mx1 = fmaxf(mx1, __shfl_xor_sync(0xffffffff, mx1, 2));
        float mn0 = fmaxf(m0, mx0), mn1 = fmaxf(m1, mx1);
        float al0 = __expf(m0 - mn0), al1 = __expf(m1 - mn1);
        m0 = mn0; m1 = mn1;
        float ls0 = 0.f, ls1 = 0.f;
#pragma unroll
        for (int nf = 0; nf < 4; nf++) {
            sf[nf][0] = __expf(sf[nf][0] - mn0);
            sf[nf][1] = __expf(sf[nf][1] - mn0);
            sf[nf][2] = __expf(sf[nf][2] - mn1);
            sf[nf][3] = __expf(sf[nf][3] - mn1);
            ls0 += sf[nf][0] + sf[nf][1];
            ls1 += sf[nf][2] + sf[nf][3];
        }
        l0 = l0 * al0 + ls0;
        l1 = l1 * al1 + ls1;
#pragma unroll
        for (int nf = 0; nf < 16; nf++) {
            of[nf][0] *= al0; of[nf][1] *= al0;
            of[nf][2] *= al1; of[nf][3] *= al1;
        }

        uint32_t vBase = smBase + (F_V(st) + vrow * FSTR) * 2;
#pragma unroll
        for (int t = 0; t < 2; t++) {
            uint32_t pah[4], pal[4];
#pragma unroll
            for (int q = 0; q < 2; q++) {
                fp16 h0, e0, h1, e1, h2, e2, h3, e3;
                split1h(sf[2 * t + q][0], h0, e0); split1h(sf[2 * t + q][1], h1, e1);
                split1h(sf[2 * t + q][2], h2, e2); split1h(sf[2 * t + q][3], h3, e3);
                pah[2 * q]     = packh2(h0, h1);
                pal[2 * q]     = packh2(e0, e1);
                pah[2 * q + 1] = packh2(h2, h3);
                pal[2 * q + 1] = packh2(e2, e3);
            }
#pragma unroll
            for (int nf = 0; nf < 16; nf++) {
                uint32_t vh2[2];
                uint32_t off = (t * 16 * FSTR + nf * 8) * 2;
                ldm_x2t(vh2, vBase + off);
                mma_f16(of[nf], pah, vh2);
                mma_f16(of[nf], pal, vh2);
            }
        }
        __syncthreads();
    }

    l0 += __shfl_xor_sync(0xffffffff, l0, 1);
    l0 += __shfl_xor_sync(0xffffffff, l0, 2);
    l1 += __shfl_xor_sync(0xffffffff, l1, 1);
    l1 += __shfl_xor_sync(0xffffffff, l1, 2);
    float i0 = 1.0f / l0, i1 = 1.0f / l1;
    size_t r0 = (size_t)(tok0 + myrow0) * DMODEL + h * HD;
    size_t r1 = (size_t)(tok0 + myrow1) * DMODEL + h * HD;
#pragma unroll
    for (int nf = 0; nf < 16; nf++) {
        int col = nf * 8 + 2 * tig;
        fp16 h0, e0, h1, e1;
        split1h(of[nf][0] * i0, h0, e0); split1h(of[nf][1] * i0, h1, e1);
        *(uint32_t*)&Oh[r0 + col] = packh2(h0, h1);
        *(uint32_t*)&Ol[r0 + col] = packh2(e0, e1);
        split1h(of[nf][2] * i1, h0, e0); split1h(of[nf][3] * i1, h1, e1);
        *(uint32_t*)&Oh[r1 + col] = packh2(h0, h1);
        *(uint32_t*)&Ol[r1 + col] = packh2(e0, e1);
    }
}

// ---------------- gating ----------------
__global__ void gate_k(const float* __restrict__ h, const float* __restrict__ gw,
                       int* __restrict__ tope, float* __restrict__ wgt)
{
    int tok = blockIdx.x;
    int tid = threadIdx.x;
    float s[NEXP];
#pragma unroll
    for (int e = 0; e < NEXP; e++) s[e] = 0.f;
    const float* hr = h + (size_t)tok * DMODEL;
    for (int d = tid; d < DMODEL; d += 128) {
        float hv = hr[d];
#pragma unroll
        for (int e = 0; e < NEXP; e++) s[e] += hv * gw[d * NEXP + e];
    }
    __shared__ float red[NEXP][128];
#pragma unroll
    for (int e = 0; e < NEXP; e++) red[e][tid] = s[e];
    __syncthreads();
    for (int st = 64; st > 0; st >>= 1) {
        if (tid < st)
#pragma unroll
            for (int e = 0; e < NEXP; e++) red[e][tid] += red[e][tid + st];
        __syncthreads();
    }
    if (tid == 0) {
        float l[NEXP];
#pragma unroll
        for (int e = 0; e < NEXP; e++) l[e] = red[e][0];
        int i0 = 0;
#pragma unroll
        for (int e = 1; e < NEXP; e++) if (l[e] > l[i0]) i0 = e;
        int i1 = -1;
#pragma unroll
        for (int e = 0; e < NEXP; e++)
            if (e != i0 && (i1 < 0 || l[e] > l[i1])) i1 = e;
        float z = expf(l[i1] - l[i0]);
        float w0 = 1.0f / (1.0f + z);
        tope[tok * 2]     = i0;  wgt[tok * 2]     = w0;
        tope[tok * 2 + 1] = i1;  wgt[tok * 2 + 1] = 1.0f - w0;
    }
}

// ---------------- bucketize ----------------
__global__ void bucketize_k()
{
    __shared__ int sc[NEXP], cur[NEXP];
    int tid = threadIdx.x;
    if (tid < NEXP) sc[tid] = 0;
    __syncthreads();
    for (int a = tid; a < NASSIGN; a += 256) atomicAdd(&sc[g_tope[a]], 1);
    __syncthreads();
    if (tid == 0) {
        int o = 0;
        for (int e = 0; e < NEXP; e++) {
            g_cnt[e] = sc[e]; g_off[e] = o; cur[e] = o; o += sc[e];
        }
    }
    __syncthreads();
    for (int a = tid; a < NASSIGN; a += 256) {
        int e = g_tope[a];
        int p = atomicAdd(&cur[e], 1);
        g_perm[p] = a >> 1;
        g_slot[a] = p;
    }
}

// ---------------- combine ----------------
__global__ void combine_k(float* __restrict__ out, int total)
{
    int idx = blockIdx.x * blockDim.x + threadIdx.x;
    if (idx >= total) return;
    int tok = idx >> 11;
    int d   = idx & 2047;
    int s0 = g_slot[tok * 2],     s1 = g_slot[tok * 2 + 1];
    float w0 = g_wgt[tok * 2],    w1 = g_wgt[tok * 2 + 1];
    out[idx] = g_inter[idx]
             + w0 * g_eout[(size_t)s0 * DMODEL + d]
             + w1 * g_eout[(size_t)s1 * DMODEL + d];
}

// =============================== launcher ===============================
extern "C" void kernel_launch(void* const* d_in, const int* in_sizes, int n_in,
                              void* d_out, int out_size)
{
    const float* inputs  = (const float*)d_in[0];
    const float* pre_s   = (const float*)d_in[1];
    const float* post_s  = (const float*)d_in[2];
    const float* wq      = (const float*)d_in[3];
    const float* wk      = (const float*)d_in[4];
    const float* wv      = (const float*)d_in[5];
    const float* wo_attn = (const float*)d_in[6];
    const float* gate_w  = (const float*)d_in[7];
    const float* wi0     = (const float*)d_in[8];
    const float* wi1     = (const float*)d_in[9];
    const float* wo_mlp  = (const float*)d_in[10];
    const int*   seg     = (const int*)d_in[11];
    const int*   pos     = (const int*)d_in[12];
    float* out = (float*)d_out;

    float *qkv, *inter, *h, *eout, *wgt;
    int *perm, *slot, *tope, *cnt, *off;
    fp16 *lnxh,*lnxl,*cth,*ctl,*hh,*hl,*acth,*actl;
    fp16 *qkvw,*wo,*w01,*wom,*qh,*ql,*kh,*vh;
    cudaGetSymbolAddress((void**)&qkv,  g_qkv);
    cudaGetSymbolAddress((void**)&inter,g_inter);
    cudaGetSymbolAddress((void**)&h,    g_hbuf);
    cudaGetSymbolAddress((void**)&eout, g_eout);
    cudaGetSymbolAddress((void**)&perm, g_perm);
    cudaGetSymbolAddress((void**)&slot, g_slot);
    cudaGetSymbolAddress((void**)&tope, g_tope);
    cudaGetSymbolAddress((void**)&wgt,  g_wgt);
    cudaGetSymbolAddress((void**)&cnt,  g_cnt);
    cudaGetSymbolAddress((void**)&off,  g_off);
    cudaGetSymbolAddress((void**)&lnxh, g_lnxh);
    cudaGetSymbolAddress((void**)&lnxl, g_lnxl);
    cudaGetSymbolAddress((void**)&cth,  g_cth);
    cudaGetSymbolAddress((void**)&ctl,  g_ctl);
    cudaGetSymbolAddress((void**)&hh,   g_hh);
    cudaGetSymbolAddress((void**)&hl,   g_hl);
    cudaGetSymbolAddress((void**)&acth, g_acth);
    cudaGetSymbolAddress((void**)&actl, g_actl);
    cudaGetSymbolAddress((void**)&qkvw, g_qkvw);
    cudaGetSymbolAddress((void**)&wo,   g_wo);
    cudaGetSymbolAddress((void**)&w01,  g_w01);
    cudaGetSymbolAddress((void**)&wom,  g_wom);
    cudaGetSymbolAddress((void**)&qh,   g_qh);
    cudaGetSymbolAddress((void**)&ql,   g_ql);
    cudaGetSymbolAddress((void**)&kh,   g_kh);
    cudaGetSymbolAddress((void**)&vh,   g_vh);

    cudaFuncSetAttribute(fp16_gemm_k, cudaFuncAttributeMaxDynamicSharedMemorySize,
                         SMEM_GEMM_BYTES);
    cudaFuncSetAttribute(flash2_k, cudaFuncAttributeMaxDynamicSharedMemorySize,
                         FLASH_SMEM_BYTES);

    // 0) weight converts (fp16 single plane)
    {
        long long t;
        t = (long long)DMODEL * DMODEL;
        wsplit_k<<<dim3((unsigned)((t + 255) / 256), 1), 256>>>(
            wq, qkvw, DMODEL, QKVN, 0, 1, 0, 0, t);
        t = (long long)DMODEL * (HKVN * HD);
        wsplit_k<<<dim3((unsigned)((t + 255) / 256), 1), 256>>>(
            wk, qkvw, HKVN * HD, QKVN, 2048, 1, 0, 0, t);
        wsplit_k<<<dim3((unsigned)((t + 255) / 256), 1), 256>>>(
            wv, qkvw, HKVN * HD, QKVN, 3072, 1, 0, 0, t);
        t = (long long)DMODEL * DMODEL;
        wsplit_k<<<dim3((unsigned)((t + 255) / 256), 1), 256>>>(
            wo_attn, wo, DMODEL, DMODEL, 0, 1, 0, 0, t);
        t = (long long)DMODEL * FDIM;
        wsplit_k<<<dim3((unsigned)((t + 255) / 256), NEXP), 256>>>(
            wi0, w01, FDIM, 2 * FDIM, 0, 2,
            (long long)DMODEL * FDIM, (long long)DMODEL * 2 * FDIM, t);
        wsplit_k<<<dim3((unsigned)((t + 255) / 256), NEXP), 256>>>(
            wi1, w01, FDIM, 2 * FDIM, 1, 2,
            (long long)DMODEL * FDIM, (long long)DMODEL * 2 * FDIM, t);
        t = (long long)FDIM * DMODEL;
        wsplit_k<<<dim3((unsigned)((t + 255) / 256), NEXP), 256>>>(
            wo_mlp, wom, DMODEL, DMODEL, 0, 1,
            (long long)FDIM * DMODEL, (long long)FDIM * DMODEL, t);
    }

    // 1) pre-attention RMSNorm -> lnx hi/lo
    rmsnorm_split_k<<<NT, 256>>>(inputs, pre_s, nullptr, lnxh, lnxl);

    // 2) fused QKV projection -> qkv fp32
    fp16_gemm_k<<<dim3(QKVN/128, NT/128, 1), 256, SMEM_GEMM_BYTES>>>(
        lnxh, lnxl, qkvw, nullptr, qkv, nullptr, nullptr,
        NT, QKVN, DMODEL, nullptr, nullptr, nullptr, 0, 0);

    // 3) RoPE + splits
    {
        int totq = NT * HQN * 64;
        rope_split_k<<<(totq + 255) / 256, 256>>>(qkv, pos, 0, HQN,
            0.08838834764831845f, qh, ql, totq);
        int totk = NT * HKVN * 64;
        rope1_k<<<(totk + 255) / 256, 256>>>(qkv, pos, 2048, HKVN, kh, totk);
        int totv = NT * HKVN * HD;
        splitv1_k<<<(totv + 255) / 256, 256>>>(qkv, vh, totv);
    }

    // 4) flash attention -> ctx hi/lo
    flash2_k<<<dim3(S_LEN/FQT, HQN, BATCH), 128, FLASH_SMEM_BYTES>>>(
        qh, ql, kh, vh, seg, cth, ctl);

    // 5) O projection + residual -> inter
    fp16_gemm_k<<<dim3(DMODEL/128, NT/128, 1), 256, SMEM_GEMM_BYTES>>>(
        cth, ctl, wo, inputs, inter, nullptr, nullptr,
        NT, DMODEL, DMODEL, nullptr, nullptr, nullptr, 0, 0);

    // 6) post-attention RMSNorm -> h fp32 + hi/lo
    rmsnorm_split_k<<<NT, 256>>>(inter, post_s, h, hh, hl);

    // 7) gating
    gate_k<<<NT, 128>>>(h, gate_w, tope, wgt);

    // 8) bucketize
    bucketize_k<<<1, 256>>>();

    // 9) fused MoE up-projection + SiLU (interleaved wi0/wi1) -> act hi/lo
    fp16_gemm_k<<<dim3((2*FDIM)/128, NASSIGN/128, NEXP), 256, SMEM_GEMM_BYTES>>>(
        hh, hl, w01, nullptr, nullptr, acth, actl,
        0, 2*FDIM, DMODEL, perm, cnt, off, (long long)DMODEL * 2 * FDIM, 1);

    // 10) MoE down-projection -> eout
    fp16_gemm_k<<<dim3(DMODEL/128, NASSIGN/128, NEXP), 256, SMEM_GEMM_BYTES>>>(
        acth, actl, wom, nullptr, eout, nullptr, nullptr,
        0, DMODEL, FDIM, nullptr, cnt, off, (long long)FDIM * DMODEL, 0);

    // 11) combine
    combine_k<<<(NT * DMODEL) / 256, 256>>>(out, NT * DMODEL);
}

// round 7
// speedup vs baseline: 7.5446x; 1.7447x over previous
#include <cuda_runtime.h>
#include <cuda_fp16.h>
#include <cstdint>
#include <math.h>

#define NT      4096       // B*S tokens
#define DMODEL  2048
#define S_LEN   2048
#define BATCH   2
#define HQN     16
#define HKVN    8
#define HD      128
#define NEXP    8
#define FDIM    4096
#define NASSIGN (NT*2)
#define QKVN    4096       // 2048 q + 1024 k + 1024 v

typedef __half fp16;

// ---------------- scratch ----------------
__device__ float g_qkv [NT*QKVN];
__device__ float g_inter[NT*DMODEL];
__device__ float g_hbuf[NT*DMODEL];
__device__ float g_eout[NASSIGN*DMODEL];
__device__ int   g_perm[NASSIGN];
__device__ int   g_slot[NASSIGN];
__device__ int   g_tope[NASSIGN];
__device__ float g_wgt [NASSIGN];
__device__ int   g_cnt [NEXP];
__device__ int   g_off [NEXP];

// fp16 activation planes (single plane)
__device__ fp16 g_lnx [NT*DMODEL];
__device__ fp16 g_ctx [NT*DMODEL];
__device__ fp16 g_hh  [NT*DMODEL];
__device__ fp16 g_act [NASSIGN*FDIM];
// fp16 weights
__device__ fp16 g_qkvw[DMODEL*QKVN];
__device__ fp16 g_wo  [DMODEL*DMODEL];
__device__ fp16 g_w01 [(size_t)NEXP*DMODEL*2*FDIM];   // interleaved wi0/wi1
__device__ fp16 g_wom [(size_t)NEXP*FDIM*DMODEL];
// attention operands
__device__ fp16 g_qh[NT*HQN*HD];
__device__ fp16 g_kh[NT*HKVN*HD];
__device__ fp16 g_vh[NT*HKVN*HD];

__device__ __forceinline__ uint32_t packh2(fp16 a, fp16 b) {
    __half2 p; p.x = a; p.y = b;
    return *(uint32_t*)&p;
}
__device__ __forceinline__ void cp16(uint32_t dst, const void* src) {
    asm volatile("cp.async.cg.shared.global [%0], [%1], 16;" :: "r"(dst), "l"(src));
}
__device__ __forceinline__ void cp16_zero(uint32_t dst, const void* src) {
    asm volatile("cp.async.cg.shared.global [%0], [%1], 16, 0;" :: "r"(dst), "l"(src));
}
#define CP_COMMIT() asm volatile("cp.async.commit_group;" ::: "memory")

__device__ __forceinline__ void ldm_x4(uint32_t* r, uint32_t addr) {
    asm volatile("ldmatrix.sync.aligned.m8n8.x4.shared.b16 {%0,%1,%2,%3}, [%4];"
        : "=r"(r[0]), "=r"(r[1]), "=r"(r[2]), "=r"(r[3]) : "r"(addr));
}
__device__ __forceinline__ void ldm_x2t(uint32_t* r, uint32_t addr) {
    asm volatile("ldmatrix.sync.aligned.m8n8.x2.trans.shared.b16 {%0,%1}, [%2];"
        : "=r"(r[0]), "=r"(r[1]) : "r"(addr));
}
__device__ __forceinline__ void mma_f16(float* c, const uint32_t* a, const uint32_t* b) {
    asm volatile(
        "mma.sync.aligned.m16n8k16.row.col.f32.f16.f16.f32 "
        "{%0,%1,%2,%3}, {%4,%5,%6,%7}, {%8,%9}, {%0,%1,%2,%3};"
        : "+f"(c[0]), "+f"(c[1]), "+f"(c[2]), "+f"(c[3])
        : "r"(a[0]), "r"(a[1]), "r"(a[2]), "r"(a[3]), "r"(b[0]), "r"(b[1]));
}

// ---------------- weight convert (fp16, optional column interleave) ----------------
__global__ void wsplit_k(const float* __restrict__ src, fp16* __restrict__ dst,
                         int ncol, int dstStride, int colOff, int colMul,
                         long long srcZ, long long dstZ, long long total)
{
    long long i = (long long)blockIdx.x * blockDim.x + threadIdx.x;
    if (i >= total) return;
    int z = blockIdx.y;
    const float* s = src + (long long)z * srcZ;
    fp16* d = dst + (long long)z * dstZ;
    int kr = (int)(i / ncol);
    int n  = (int)(i % ncol);
    d[(long long)kr * dstStride + colOff + (long long)n * colMul] = __float2half(s[i]);
}

// ---------------- RMSNorm (+optional fp32 out, fp16 out) ----------------
__global__ void rmsnorm_split_k(const float* __restrict__ x, const float* __restrict__ sc,
                                float* __restrict__ yf, fp16* __restrict__ yh)
{
    int row = blockIdx.x;
    int tid = threadIdx.x;
    const float* xr = x + (size_t)row * DMODEL;
    float ss = 0.f;
    for (int d = tid; d < DMODEL; d += 256) { float v = xr[d]; ss += v * v; }
    __shared__ float red[256];
    red[tid] = ss; __syncthreads();
    for (int st = 128; st > 0; st >>= 1) {
        if (tid < st) red[tid] += red[tid + st];
        __syncthreads();
    }
    float inv = rsqrtf(red[0] / (float)DMODEL + 1e-6f);
    size_t base = (size_t)row * DMODEL;
    for (int d = tid; d < DMODEL; d += 256) {
        float v = xr[d] * inv * sc[d];
        if (yf) yf[base + d] = v;
        yh[base + d] = __float2half(v);
    }
}

// ================= fp16 tensor-core GEMM =================
// BM=128,BN=128,BK=32; 8 warps, warp tile 64x32; single fp16 planes.
#define ASTR 40
#define BSTR 136
#define OFF_A(s) ((s)*5120)
#define OFF_B(s) (10240 + (s)*4352)
#define SMEM_GEMM_BYTES (18944*2)

__global__ __launch_bounds__(256, 2)
void fp16_gemm_k(const fp16* __restrict__ Ag, const fp16* __restrict__ Bg,
                 const float* __restrict__ res, float* __restrict__ Cf,
                 fp16* __restrict__ SH,
                 int M, int N, int K,
                 const int* __restrict__ perm,
                 const int* __restrict__ cnts, const int* __restrict__ offs,
                 long long strideB, int mode)
{
    extern __shared__ fp16 sm[];
    int rowBase = 0;
    const fp16* B = Bg;
    if (cnts) {
        int e = blockIdx.z;
        M = cnts[e];
        rowBase = offs[e];
        B = Bg + (long long)e * strideB;
    }
    int bm = blockIdx.y * 128;
    if (bm >= M) return;
    int bn = blockIdx.x * 128;

    int tid  = threadIdx.x;
    int lane = tid & 31;
    int w    = tid >> 5;
    int wm   = w & 1;
    int wn   = w >> 1;

    uint32_t smBase = (uint32_t)__cvta_generic_to_shared(sm);
    uint32_t aLane  = ((lane & 15) * ASTR + (lane >> 4) * 8) * 2;
    uint32_t bLane  = ((lane & 15) * BSTR) * 2;

    int rA  = tid >> 1;
    int ac0 = (tid & 1) * 16;
    int aIdx = -1;
    if (bm + rA < M) { int r = rowBase + bm + rA; aIdx = perm ? perm[r] : r; }

    int rB  = tid >> 3;
    int bc0 = (tid & 7) * 8;

    float acc[4][4][4];
#pragma unroll
    for (int i = 0; i < 4; i++)
#pragma unroll
        for (int j = 0; j < 4; j++)
#pragma unroll
            for (int c = 0; c < 4; c++) acc[i][j][c] = 0.f;

    const int NKT = K >> 5;

    auto prefetch = [&](int kt, int st) {
        int k0 = kt << 5;
        uint32_t dA = smBase + (OFF_A(st) + rA * ASTR + ac0) * 2;
        if (aIdx >= 0) {
            const fp16* sa = Ag + (size_t)aIdx * K + k0 + ac0;
            cp16(dA, sa);      cp16(dA + 16, sa + 8);
        } else {
            cp16_zero(dA, Ag); cp16_zero(dA + 16, Ag);
        }
        uint32_t dB = smBase + (OFF_B(st) + rB * BSTR + bc0) * 2;
        const fp16* sb = B + (size_t)(k0 + rB) * N + bn + bc0;
        cp16(dB, sb);       cp16(dB + 128, sb + 64);
    };

    prefetch(0, 0);
    CP_COMMIT();

    for (int kt = 0; kt < NKT; kt++) {
        int st = kt & 1;
        if (kt + 1 < NKT) {
            prefetch(kt + 1, st ^ 1);
            CP_COMMIT();
            asm volatile("cp.async.wait_group 1;" ::: "memory");
        } else {
            asm volatile("cp.async.wait_group 0;" ::: "memory");
        }
        __syncthreads();

        uint32_t aBase = smBase + (OFF_A(st) + wm * 64 * ASTR) * 2 + aLane;
        uint32_t bBase = smBase + (OFF_B(st)) * 2 + wn * 32 * 2 + bLane;

#pragma unroll
        for (int ks = 0; ks < 2; ks++) {
            uint32_t ah[4][4];
#pragma unroll
            for (int mf = 0; mf < 4; mf++) {
                uint32_t off = mf * (16 * ASTR * 2) + ks * 32;
                ldm_x4(ah[mf], aBase + off);
            }
            uint32_t bh[4][2];
#pragma unroll
            for (int nf = 0; nf < 4; nf++) {
                uint32_t off = nf * 16 + ks * (16 * BSTR * 2);
                ldm_x2t(bh[nf], bBase + off);
            }
#pragma unroll
            for (int mf = 0; mf < 4; mf++)
#pragma unroll
                for (int nf = 0; nf < 4; nf++)
                    mma_f16(acc[mf][nf], ah[mf], bh[nf]);
        }
        __syncthreads();
    }

    int g   = lane >> 2;
    int tig = lane & 3;
#pragma unroll
    for (int mf = 0; mf < 4; mf++) {
        int row0 = bm + wm * 64 + mf * 16 + g;
        int row1 = row0 + 8;
#pragma unroll
        for (int nf = 0; nf < 4; nf++) {
            int col = bn + wn * 32 + nf * 8 + tig * 2;
            if (mode == 0) {
                if (row0 < M) {
                    size_t o = (size_t)(rowBase + row0) * N + col;
                    float2 v = make_float2(acc[mf][nf][0], acc[mf][nf][1]);
                    if (res) { float2 r = *(const float2*)&res[o]; v.x += r.x; v.y += r.y; }
                    *(float2*)&Cf[o] = v;
                }
                if (row1 < M) {
                    size_t o = (size_t)(rowBase + row1) * N + col;
                    float2 v = make_float2(acc[mf][nf][2], acc[mf][nf][3]);
                    if (res) { float2 r = *(const float2*)&res[o]; v.x += r.x; v.y += r.y; }
                    *(float2*)&Cf[o] = v;
                }
            } else {
                // interleaved silu: even col = gate (wi0), odd col = value (wi1)
                int f = col >> 1;
                if (row0 < M) {
                    size_t o = (size_t)(rowBase + row0) * (size_t)(N >> 1) + f;
                    float a = acc[mf][nf][0], b = acc[mf][nf][1];
                    SH[o] = __float2half((a / (1.0f + __expf(-a))) * b);
                }
                if (row1 < M) {
                    size_t o = (size_t)(rowBase + row1) * (size_t)(N >> 1) + f;
                    float a = acc[mf][nf][2], b = acc[mf][nf][3];
                    SH[o] = __float2half((a / (1.0f + __expf(-a))) * b);
                }
            }
        }
    }
}

// ---------------- RoPE -> single fp16 plane ----------------
__global__ void rope1_k(const float* __restrict__ qkv, const int* __restrict__ pos,
                        int srcOff, int nheads, float scale,
                        fp16* __restrict__ outH, int total)
{
    int idx = blockIdx.x * blockDim.x + threadIdx.x;
    if (idx >= total) return;
    int i   = idx & 63;
    int th  = idx >> 6;
    int h   = th % nheads;
    int tok = th / nheads;
    float freq = powf(10000.0f, -(float)i / 64.0f);
    float ang = (float)pos[tok] * freq;
    float c = cosf(ang), s = sinf(ang);
    const float* row = qkv + (size_t)tok * QKVN + srcOff + h * HD;
    float x1 = row[i], x2 = row[i + 64];
    size_t o = (size_t)tok * (nheads * HD) + h * HD;
    outH[o + i]      = __float2half((x1 * c - x2 * s) * scale);
    outH[o + i + 64] = __float2half((x2 * c + x1 * s) * scale);
}

__global__ void splitv1_k(const float* __restrict__ qkv, fp16* __restrict__ vh, int total)
{
    int idx = blockIdx.x * blockDim.x + threadIdx.x;
    if (idx >= total) return;
    int tok = idx >> 10;
    int d   = idx & 1023;
    vh[idx] = __float2half(qkv[(size_t)tok * QKVN + 3072 + d]);
}

// ================= fp16 flash attention =================
// QT=64, KT=32, 4 warps; all single-plane fp16.
#define FQT 64
#define FKT 32
#define FSTR 136
#define F_Q 0
#define F_K(s) (8704 + (s)*4352)
#define F_V(s) (17408 + (s)*4352)
#define FLASH_SMEM_BYTES (26112*2)

__global__ __launch_bounds__(128)
void flash2_k(const fp16* __restrict__ Qh,
              const fp16* __restrict__ Kh, const fp16* __restrict__ Vh,
              const int* __restrict__ seg, fp16* __restrict__ Oh)
{
    extern __shared__ fp16 fsm[];
    __shared__ int Sq[FQT];
    __shared__ int Sk[2][FKT];

    int tid  = threadIdx.x;
    int lane = tid & 31;
    int w    = tid >> 5;
    int g    = lane >> 2;
    int tig  = lane & 3;

    int q0  = blockIdx.x * FQT;
    int h   = blockIdx.y;
    int b   = blockIdx.z;
    int tok0 = b * S_LEN;
    int hk  = h >> 1;

    uint32_t smBase = (uint32_t)__cvta_generic_to_shared(fsm);

    {
        int r  = tid >> 1;
        int c0 = (tid & 1) * 64;
        const fp16* sq = Qh + (size_t)(tok0 + q0 + r) * (HQN * HD) + h * HD + c0;
        uint32_t dq = smBase + (F_Q + r * FSTR + c0) * 2;
#pragma unroll
        for (int j = 0; j < 8; j++) cp16(dq + j * 16, sq + j * 8);
    }
    if (tid < FQT) Sq[tid] = seg[tok0 + q0 + tid];

    auto prefetch = [&](int kt, int st) {
        int k0 = kt * FKT;
        int r  = tid >> 2;
        int c0 = (tid & 3) * 32;
        size_t gbase = (size_t)(tok0 + k0 + r) * (HKVN * HD) + hk * HD + c0;
        uint32_t dk = smBase + (F_K(st) + r * FSTR + c0) * 2;
        uint32_t dv = smBase + (F_V(st) + r * FSTR + c0) * 2;
#pragma unroll
        for (int j = 0; j < 4; j++) {
            cp16(dk + j * 16, Kh + gbase + j * 8);
            cp16(dv + j * 16, Vh + gbase + j * 8);
        }
        if (tid < FKT) Sk[st][tid] = seg[tok0 + k0 + tid];
    };

    prefetch(0, 0);
    CP_COMMIT();

    float of[16][4];
#pragma unroll
    for (int nf = 0; nf < 16; nf++)
#pragma unroll
        for (int c = 0; c < 4; c++) of[nf][c] = 0.f;
    float m0 = -1e9f, m1 = -1e9f, l0 = 0.f, l1 = 0.f;

    uint32_t qAddr = smBase + (F_Q + (w * 16 + (lane & 15)) * FSTR + (lane >> 4) * 8) * 2;
    int ktokoff = (lane & 7) + ((lane >> 4) << 3);
    int kdhalf  = ((lane >> 3) & 1) * 8;
    int vrow    = lane & 15;

    int ktend = (q0 + FQT - 1) / FKT;
    int myrow0 = q0 + w * 16 + g;
    int myrow1 = myrow0 + 8;
    int sq0 = 0, sq1 = 0;

    for (int kt = 0; kt <= ktend; kt++) {
        int st = kt & 1;
        if (kt + 1 <= ktend) {
            prefetch(kt + 1, st ^ 1);
            CP_COMMIT();
            asm volatile("cp.async.wait_group 1;" ::: "memory");
        } else {
            asm volatile("cp.async.wait_group 0;" ::: "memory");
        }
        __syncthreads();
        if (kt == 0) { sq0 = Sq[w * 16 + g]; sq1 = Sq[w * 16 + g + 8]; }
        int k0 = kt * FKT;

        float sf[4][4];
#pragma unroll
        for (int nf = 0; nf < 4; nf++)
#pragma unroll
            for (int c = 0; c < 4; c++) sf[nf][c] = 0.f;

        uint32_t kBase = smBase + (F_K(st) + ktokoff * FSTR + kdhalf) * 2;

#pragma unroll
        for (int kk = 0; kk < 8; kk++) {
            uint32_t qh4[4];
            ldm_x4(qh4, qAddr + kk * 32);
#pragma unroll
            for (int p = 0; p < 2; p++) {
                uint32_t kh4[4];
                uint32_t off = (p * 16 * FSTR + kk * 16) * 2;
                ldm_x4(kh4, kBase + off);
                mma_f16(sf[2 * p],     qh4, kh4);
                mma_f16(sf[2 * p + 1], qh4, kh4 + 2);
            }
        }

#pragma unroll
        for (int nf = 0; nf < 4; nf++) {
            int c0g = k0 + nf * 8 + 2 * tig;
            int sk0 = Sk[st][nf * 8 + 2 * tig];
            int sk1 = Sk[st][nf * 8 + 2 * tig + 1];
            if (c0g > myrow0     || sk0 != sq0) sf[nf][0] = -1e9f;
            if (c0g + 1 > myrow0 || sk1 != sq0) sf[nf][1] = -1e9f;
            if (c0g > myrow1     || sk0 != sq1) sf[nf][2] = -1e9f;
            if (c0g + 1 > myrow1 || sk1 != sq1) sf[nf][3] = -1e9f;
        }
        float mx0 = -1e9f, mx1 = -1e9f;
#pragma unroll
        for (int nf = 0; nf < 4; nf++) {
            mx0 = fmaxf(mx0, fmaxf(sf[nf][0], sf[nf][1]));
            mx1 = fmaxf(mx1, fmaxf(sf[nf][2], sf[nf][3]));
        }
        mx0 = fmaxf(mx0, __shfl_xor_sync(0xffffffff, mx0, 1));
        mx0 = fmaxf(mx0, __shfl_xor_sync(0xffffffff, mx0, 2));
        mx1 = fmaxf(mx1, __shfl_xor_sync(0xffffffff, mx1, 1));
        mx1 = fmaxf(mx1, __shfl_xor_sync(0xffffffff, mx1, 2));
        float mn0 = fmaxf(m0, mx0), mn1 = fmaxf(m1, mx1);
        float al0 = __expf(m0 - mn0), al1 = __expf(m1 - mn1);
        m0 = mn0; m1 = mn1;
        float ls0 = 0.f, ls1 = 0.f;
#pragma unroll
        for (int nf = 0; nf < 4; nf++) {
            sf[nf][0] = __expf(sf[nf][0] - mn0);
            sf[nf][1] = __expf(sf[nf][1] - mn0);
            sf[nf][2] = __expf(sf[nf][2] - mn1);
            sf[nf][3] = __expf(sf[nf][3] - mn1);
            ls0 += sf[nf][0] + sf[nf][1];
            ls1 += sf[nf][2] + sf[nf][3];
        }
        l0 = l0 * al0 + ls0;
        l1 = l1 * al1 + ls1;
#pragma unroll
        for (int nf = 0; nf < 16; nf++) {
            of[nf][0] *= al0; of[nf][1] *= al0;
            of[nf][2] *= al1; of[nf][3] *= al1;
        }

        uint32_t vBase = smBase + (F_V(st) + vrow * FSTR) * 2;
#pragma unroll
        for (int t = 0; t < 2; t++) {
            uint32_t pah[4];
#pragma unroll
            for (int q = 0; q < 2; q++) {
                pah[2 * q]     = packh2(__float2half(sf[2 * t + q][0]),
                                        __float2half(sf[2 * t + q][1]));
                pah[2 * q + 1] = packh2(__float2half(sf[2 * t + q][2]),
                                        __float2half(sf[2 * t + q][3]));
            }
#pragma unroll
            for (int nf = 0; nf < 16; nf++) {
                uint32_t vh2[2];
                uint32_t off = (t * 16 * FSTR + nf * 8) * 2;
                ldm_x2t(vh2, vBase + off);
                mma_f16(of[nf], pah, vh2);
            }
        }
        __syncthreads();
    }

    l0 += __shfl_xor_sync(0xffffffff, l0, 1);
    l0 += __shfl_xor_sync(0xffffffff, l0, 2);
    l1 += __shfl_xor_sync(0xffffffff, l1, 1);
    l1 += __shfl_xor_sync(0xffffffff, l1, 2);
    float i0 = 1.0f / l0, i1 = 1.0f / l1;
    size_t r0 = (size_t)(tok0 + myrow0) * DMODEL + h * HD;
    size_t r1 = (size_t)(tok0 + myrow1) * DMODEL + h * HD;
#pragma unroll
    for (int nf = 0; nf < 16; nf++) {
        int col = nf * 8 + 2 * tig;
        *(uint32_t*)&Oh[r0 + col] = packh2(__float2half(of[nf][0] * i0),
                                           __float2half(of[nf][1] * i0));
        *(uint32_t*)&Oh[r1 + col] = packh2(__float2half(of[nf][2] * i1),
                                           __float2half(of[nf][3] * i1));
    }
}

// ---------------- gating ----------------
__global__ void gate_k(const float* __restrict__ h, const float* __restrict__ gw,
                       int* __restrict__ tope, float* __restrict__ wgt)
{
    int tok = blockIdx.x;
    int tid = threadIdx.x;
    float s[NEXP];
#pragma unroll
    for (int e = 0; e < NEXP; e++) s[e] = 0.f;
    const float* hr = h + (size_t)tok * DMODEL;
    for (int d = tid; d < DMODEL; d += 128) {
        float hv = hr[d];
#pragma unroll
        for (int e = 0; e < NEXP; e++) s[e] += hv * gw[d * NEXP + e];
    }
    __shared__ float red[NEXP][128];
#pragma unroll
    for (int e = 0; e < NEXP; e++) red[e][tid] = s[e];
    __syncthreads();
    for (int st = 64; st > 0; st >>= 1) {
        if (tid < st)
#pragma unroll
            for (int e = 0; e < NEXP; e++) red[e][tid] += red[e][tid + st];
        __syncthreads();
    }
    if (tid == 0) {
        float l[NEXP];
#pragma unroll
        for (int e = 0; e < NEXP; e++) l[e] = red[e][0];
        int i0 = 0;
#pragma unroll
        for (int e = 1; e < NEXP; e++) if (l[e] > l[i0]) i0 = e;
        int i1 = -1;
#pragma unroll
        for (int e = 0; e < NEXP; e++)
            if (e != i0 && (i1 < 0 || l[e] > l[i1])) i1 = e;
        float z = expf(l[i1] - l[i0]);
        float w0 = 1.0f / (1.0f + z);
        tope[tok * 2]     = i0;  wgt[tok * 2]     = w0;
        tope[tok * 2 + 1] = i1;  wgt[tok * 2 + 1] = 1.0f - w0;
    }
}

// ---------------- bucketize ----------------
__global__ void bucketize_k()
{
    __shared__ int sc[NEXP], cur[NEXP];
    int tid = threadIdx.x;
    if (tid < NEXP) sc[tid] = 0;
    __syncthreads();
    for (int a = tid; a < NASSIGN; a += 256) atomicAdd(&sc[g_tope[a]], 1);
    __syncthreads();
    if (tid == 0) {
        int o = 0;
        for (int e = 0; e < NEXP; e++) {
            g_cnt[e] = sc[e]; g_off[e] = o; cur[e] = o; o += sc[e];
        }
    }
    __syncthreads();
    for (int a = tid; a < NASSIGN; a += 256) {
        int e = g_tope[a];
        int p = atomicAdd(&cur[e], 1);
        g_perm[p] = a >> 1;
        g_slot[a] = p;
    }
}

// ---------------- combine ----------------
__global__ void combine_k(float* __restrict__ out, int total)
{
    int idx = blockIdx.x * blockDim.x + threadIdx.x;
    if (idx >= total) return;
    int tok = idx >> 11;
    int d   = idx & 2047;
    int s0 = g_slot[tok * 2],     s1 = g_slot[tok * 2 + 1];
    float w0 = g_wgt[tok * 2],    w1 = g_wgt[tok * 2 + 1];
    out[idx] = g_inter[idx]
             + w0 * g_eout[(size_t)s0 * DMODEL + d]
             + w1 * g_eout[(size_t)s1 * DMODEL + d];
}

// =============================== launcher ===============================
extern "C" void kernel_launch(void* const* d_in, const int* in_sizes, int n_in,
                              void* d_out, int out_size)
{
    const float* inputs  = (const float*)d_in[0];
    const float* pre_s   = (const float*)d_in[1];
    const float* post_s  = (const float*)d_in[2];
    const float* wq      = (const float*)d_in[3];
    const float* wk      = (const float*)d_in[4];
    const float* wv      = (const float*)d_in[5];
    const float* wo_attn = (const float*)d_in[6];
    const float* gate_w  = (const float*)d_in[7];
    const float* wi0     = (const float*)d_in[8];
    const float* wi1     = (const float*)d_in[9];
    const float* wo_mlp  = (const float*)d_in[10];
    const int*   seg     = (const int*)d_in[11];
    const int*   pos     = (const int*)d_in[12];
    float* out = (float*)d_out;

    float *qkv, *inter, *h, *eout, *wgt;
    int *perm, *slot, *tope, *cnt, *off;
    fp16 *lnx,*ctx,*hh,*act,*qkvw,*wo,*w01,*wom,*qh,*kh,*vh;
    cudaGetSymbolAddress((void**)&qkv,  g_qkv);
    cudaGetSymbolAddress((void**)&inter,g_inter);
    cudaGetSymbolAddress((void**)&h,    g_hbuf);
    cudaGetSymbolAddress((void**)&eout, g_eout);
    cudaGetSymbolAddress((void**)&perm, g_perm);
    cudaGetSymbolAddress((void**)&slot, g_slot);
    cudaGetSymbolAddress((void**)&tope, g_tope);
    cudaGetSymbolAddress((void**)&wgt,  g_wgt);
    cudaGetSymbolAddress((void**)&cnt,  g_cnt);
    cudaGetSymbolAddress((void**)&off,  g_off);
    cudaGetSymbolAddress((void**)&lnx,  g_lnx);
    cudaGetSymbolAddress((void**)&ctx,  g_ctx);
    cudaGetSymbolAddress((void**)&hh,   g_hh);
    cudaGetSymbolAddress((void**)&act,  g_act);
    cudaGetSymbolAddress((void**)&qkvw, g_qkvw);
    cudaGetSymbolAddress((void**)&wo,   g_wo);
    cudaGetSymbolAddress((void**)&w01,  g_w01);
    cudaGetSymbolAddress((void**)&wom,  g_wom);
    cudaGetSymbolAddress((void**)&qh,   g_qh);
    cudaGetSymbolAddress((void**)&kh,   g_kh);
    cudaGetSymbolAddress((void**)&vh,   g_vh);

    cudaFuncSetAttribute(fp16_gemm_k, cudaFuncAttributeMaxDynamicSharedMemorySize,
                         SMEM_GEMM_BYTES);
    cudaFuncSetAttribute(flash2_k, cudaFuncAttributeMaxDynamicSharedMemorySize,
                         FLASH_SMEM_BYTES);

    // 0) weight converts (fp16)
    {
        long long t;
        t = (long long)DMODEL * DMODEL;
        wsplit_k<<<dim3((unsigned)((t + 255) / 256), 1), 256>>>(
            wq, qkvw, DMODEL, QKVN, 0, 1, 0, 0, t);
        t = (long long)DMODEL * (HKVN * HD);
        wsplit_k<<<dim3((unsigned)((t + 255) / 256), 1), 256>>>(
            wk, qkvw, HKVN * HD, QKVN, 2048, 1, 0, 0, t);
        wsplit_k<<<dim3((unsigned)((t + 255) / 256), 1), 256>>>(
            wv, qkvw, HKVN * HD, QKVN, 3072, 1, 0, 0, t);
        t = (long long)DMODEL * DMODEL;
        wsplit_k<<<dim3((unsigned)((t + 255) / 256), 1), 256>>>(
            wo_attn, wo, DMODEL, DMODEL, 0, 1, 0, 0, t);
        t = (long long)DMODEL * FDIM;
        wsplit_k<<<dim3((unsigned)((t + 255) / 256), NEXP), 256>>>(
            wi0, w01, FDIM, 2 * FDIM, 0, 2,
            (long long)DMODEL * FDIM, (long long)DMODEL * 2 * FDIM, t);
        wsplit_k<<<dim3((unsigned)((t + 255) / 256), NEXP), 256>>>(
            wi1, w01, FDIM, 2 * FDIM, 1, 2,
            (long long)DMODEL * FDIM, (long long)DMODEL * 2 * FDIM, t);
        t = (long long)FDIM * DMODEL;
        wsplit_k<<<dim3((unsigned)((t + 255) / 256), NEXP), 256>>>(
            wo_mlp, wom, DMODEL, DMODEL, 0, 1,
            (long long)FDIM * DMODEL, (long long)FDIM * DMODEL, t);
    }

    // 1) pre-attention RMSNorm -> lnx fp16
    rmsnorm_split_k<<<NT, 256>>>(inputs, pre_s, nullptr, lnx);

    // 2) fused QKV projection -> qkv fp32
    fp16_gemm_k<<<dim3(QKVN/128, NT/128, 1), 256, SMEM_GEMM_BYTES>>>(
        lnx, qkvw, nullptr, qkv, nullptr,
        NT, QKVN, DMODEL, nullptr, nullptr, nullptr, 0, 0);

    // 3) RoPE + splits
    {
        int totq = NT * HQN * 64;
        rope1_k<<<(totq + 255) / 256, 256>>>(qkv, pos, 0, HQN,
            0.08838834764831845f, qh, totq);
        int totk = NT * HKVN * 64;
        rope1_k<<<(totk + 255) / 256, 256>>>(qkv, pos, 2048, HKVN, 1.0f, kh, totk);
        int totv = NT * HKVN * HD;
        splitv1_k<<<(totv + 255) / 256, 256>>>(qkv, vh, totv);
    }

    // 4) flash attention -> ctx fp16
    flash2_k<<<dim3(S_LEN/FQT, HQN, BATCH), 128, FLASH_SMEM_BYTES>>>(
        qh, kh, vh, seg, ctx);

    // 5) O projection + residual -> inter
    fp16_gemm_k<<<dim3(DMODEL/128, NT/128, 1), 256, SMEM_GEMM_BYTES>>>(
        ctx, wo, inputs, inter, nullptr,
        NT, DMODEL, DMODEL, nullptr, nullptr, nullptr, 0, 0);

    // 6) post-attention RMSNorm -> h fp32 + fp16
    rmsnorm_split_k<<<NT, 256>>>(inter, post_s, h, hh);

    // 7) gating
    gate_k<<<NT, 128>>>(h, gate_w, tope, wgt);

    // 8) bucketize
    bucketize_k<<<1, 256>>>();

    // 9) fused MoE up-projection + SiLU (interleaved wi0/wi1) -> act fp16
    fp16_gemm_k<<<dim3((2*FDIM)/128, NASSIGN/128, NEXP), 256, SMEM_GEMM_BYTES>>>(
        hh, w01, nullptr, nullptr, act,
        0, 2*FDIM, DMODEL, perm, cnt, off, (long long)DMODEL * 2 * FDIM, 1);

    // 10) MoE down-projection -> eout
    fp16_gemm_k<<<dim3(DMODEL/128, NASSIGN/128, NEXP), 256, SMEM_GEMM_BYTES>>>(
        act, wom, nullptr, eout, nullptr,
        0, DMODEL, FDIM, nullptr, cnt, off, (long long)FDIM * DMODEL, 0);

    // 11) combine
    combine_k<<<(NT * DMODEL) / 256, 256>>>(out, NT * DMODEL);
}